// round 12
// baseline (speedup 1.0000x reference)
#include <cuda_runtime.h>
#include <cuda_fp16.h>
#include <cstdint>
#include <cstddef>

#define S_LEN 2048
#define HID   4096
#define NH    32
#define HD    128
#define P3    12288   // 3*HID
#define NORM  0.08838834764831845f   // 1/sqrt(128)

// ---------------- scratch (no allocations allowed) ----------------
__device__ float  g_proj[S_LEN * P3];
__device__ float  g_attn[S_LEN * HID];
__device__ __half g_hid_h[S_LEN * HID];
__device__ __half g_wp_h[P3 * HID];
__device__ __half g_wo_h[HID * HID];
__device__ __half g_attn_h[S_LEN * HID];

// ---------------- helpers ----------------
__device__ __forceinline__ uint32_t smem_u32(const void* p) {
    uint32_t a;
    asm("{ .reg .u64 t; cvta.to.shared.u64 t, %1; cvt.u32.u64 %0, t; }" : "=r"(a) : "l"(p));
    return a;
}
__device__ __forceinline__ void cp16(uint32_t saddr, const void* gptr) {
    asm volatile("cp.async.ca.shared.global [%0], [%1], 16;" :: "r"(saddr), "l"(gptr));
}
#define CP_COMMIT() asm volatile("cp.async.commit_group;" ::: "memory")
#define CP_WAIT(n)  asm volatile("cp.async.wait_group %0;" :: "n"(n) : "memory")

__device__ __forceinline__ void ldsm4(uint32_t& r0, uint32_t& r1, uint32_t& r2, uint32_t& r3,
                                      uint32_t addr) {
    asm volatile("ldmatrix.sync.aligned.m8n8.x4.shared.b16 {%0,%1,%2,%3}, [%4];"
                 : "=r"(r0), "=r"(r1), "=r"(r2), "=r"(r3) : "r"(addr));
}

// mma.sync m16n8k16 fp16, fp32 accum
__device__ __forceinline__ void mma_fp16(float& c0, float& c1, float& c2, float& c3,
                                         uint32_t a0, uint32_t a1, uint32_t a2, uint32_t a3,
                                         uint32_t b0, uint32_t b1) {
    asm volatile(
        "mma.sync.aligned.m16n8k16.row.col.f32.f16.f16.f32 "
        "{%0,%1,%2,%3}, {%4,%5,%6,%7}, {%8,%9}, {%0,%1,%2,%3};"
        : "+f"(c0), "+f"(c1), "+f"(c2), "+f"(c3)
        : "r"(a0), "r"(a1), "r"(a2), "r"(a3), "r"(b0), "r"(b1));
}
// mma.sync m16n8k16 bf16 (attention)
__device__ __forceinline__ void mma_bf16(float& c0, float& c1, float& c2, float& c3,
                                         uint32_t a0, uint32_t a1, uint32_t a2, uint32_t a3,
                                         uint32_t b0, uint32_t b1) {
    asm volatile(
        "mma.sync.aligned.m16n8k16.row.col.f32.bf16.bf16.f32 "
        "{%0,%1,%2,%3}, {%4,%5,%6,%7}, {%8,%9}, {%0,%1,%2,%3};"
        : "+f"(c0), "+f"(c1), "+f"(c2), "+f"(c3)
        : "r"(a0), "r"(a1), "r"(a2), "r"(a3), "r"(b0), "r"(b1));
}
__device__ __forceinline__ void split_pair(float x0, float x1, uint32_t& hp, uint32_t& lp) {
    uint16_t h0, h1, l0, l1;
    asm("cvt.rn.bf16.f32 %0, %1;" : "=h"(h0) : "f"(x0));
    asm("cvt.rn.bf16.f32 %0, %1;" : "=h"(h1) : "f"(x1));
    float r0 = x0 - __uint_as_float((uint32_t)h0 << 16);
    float r1 = x1 - __uint_as_float((uint32_t)h1 << 16);
    asm("cvt.rn.bf16.f32 %0, %1;" : "=h"(l0) : "f"(r0));
    asm("cvt.rn.bf16.f32 %0, %1;" : "=h"(l1) : "f"(r1));
    asm("mov.b32 %0, {%1, %2};" : "=r"(hp) : "h"(h0), "h"(h1));
    asm("mov.b32 %0, {%1, %2};" : "=r"(lp) : "h"(l0), "h"(l1));
}

// ---------------- fp32 -> fp16 convert ----------------
__global__ __launch_bounds__(256) void f2h_kernel(const float* __restrict__ src,
                                                  __half* __restrict__ dst, int n) {
    int i = (blockIdx.x * blockDim.x + threadIdx.x) * 8;
    if (i >= n) return;
    float4 a = *(const float4*)(src + i);
    float4 b = *(const float4*)(src + i + 4);
    __half2 h0 = __floats2half2_rn(a.x, a.y);
    __half2 h1 = __floats2half2_rn(a.z, a.w);
    __half2 h2 = __floats2half2_rn(b.x, b.y);
    __half2 h3 = __floats2half2_rn(b.z, b.w);
    uint4 v = {*(uint32_t*)&h0, *(uint32_t*)&h1, *(uint32_t*)&h2, *(uint32_t*)&h3};
    *(uint4*)(dst + i) = v;
}

// ---------------- fp16 cp.async + ldmatrix GEMM: C = A * B^T ----------------
// Block 128x256x64, 256 threads (8 warps 2x4), warp tile 64x64, 3-stage cp.async.
// BK=64 halves barrier count vs R10; KW=36 keeps ldmatrix conflict-free.
#define KW    36
#define NSTG  3
#define AW    (128 * KW)                       // A words per stage
#define STGW  ((128 + 256) * KW)               // 13824 words per stage
#define GEMM_SMEM (NSTG * STGW * 4)            // 165888 B

__global__ __launch_bounds__(256, 1) void gemm_fp16ca(const __half* __restrict__ A,
                                                      const __half* __restrict__ B,
                                                      float* __restrict__ C,
                                                      int M, int N, int K) {
    extern __shared__ uint32_t sm[];
    const int t = threadIdx.x;
    const int w = t >> 5, lane = t & 31;
    const int wm = w >> 2, wn = w & 3;         // 2x4 warp grid, warp tile 64x64
    const int g = lane >> 2, cc = lane & 3;
    const int m0 = blockIdx.y * 128, n0 = blockIdx.x * 256;
    const int KT = K >> 6;
    const uint32_t sbase = smem_u32(sm);

    // cp.async: A 1024 chunks (4/thread: row t>>1, 64B half), B 2048 (8/thread: row t)
    const int ar = t >> 1, ac = (t & 1) * 4;   // chunk index 0..7 within row
    const __half* AgA = A + (size_t)(m0 + ar) * K + ac * 8;
    const uint32_t saA = sbase + (ar * KW + ac * 4) * 4;
    const int br = t;
    const __half* BgB = B + (size_t)(n0 + br) * K;
    const uint32_t saB = sbase + AW * 4 + (br * KW) * 4;

    // ldmatrix per-lane word offsets (within stage)
    const int lrow = lane & 7, sel = lane >> 3;
    uint32_t a_woff[4], b_woff[4];
#pragma unroll
    for (int mt = 0; mt < 4; mt++)
        a_woff[mt] = (uint32_t)((wm * 64 + mt * 16 + lrow + (sel & 1) * 8) * KW +
                                (sel >> 1) * 4);
#pragma unroll
    for (int p = 0; p < 4; p++)
        b_woff[p] = (uint32_t)(AW + (wn * 64 + p * 16 + (sel >> 1) * 8 + lrow) * KW +
                               (sel & 1) * 4);

    // prologue: stages 0..NSTG-2
#pragma unroll
    for (int s = 0; s < NSTG - 1; s++) {
        const uint32_t so = s * STGW * 4;
        const size_t ko = (size_t)s * 64;
#pragma unroll
        for (int j = 0; j < 4; j++)
            cp16(saA + so + j * 16, AgA + ko + j * 8);
#pragma unroll
        for (int j = 0; j < 8; j++)
            cp16(saB + so + j * 16, BgB + ko + j * 8);
        CP_COMMIT();
    }

    float acc[4][8][4];
#pragma unroll
    for (int mt = 0; mt < 4; mt++)
#pragma unroll
        for (int nt = 0; nt < 8; nt++)
#pragma unroll
            for (int q = 0; q < 4; q++) acc[mt][nt][q] = 0.f;

    for (int kt = 0; kt < KT; kt++) {
        CP_WAIT(1);
        __syncthreads();
        if (kt + NSTG - 1 < KT) {
            const uint32_t so = ((kt + NSTG - 1) % NSTG) * STGW * 4;
            const size_t ko = (size_t)(kt + NSTG - 1) * 64;
#pragma unroll
            for (int j = 0; j < 4; j++)
                cp16(saA + so + j * 16, AgA + ko + j * 8);
#pragma unroll
            for (int j = 0; j < 8; j++)
                cp16(saB + so + j * 16, BgB + ko + j * 8);
        }
        CP_COMMIT();

        const uint32_t stgoff = sbase + ((kt % NSTG) * STGW) * 4;
#pragma unroll
        for (int hh = 0; hh < 4; hh++) {       // four k16 chunks
            const uint32_t kwb = stgoff + hh * 8 * 4;
            uint32_t af[4][4], bf[4][4];
#pragma unroll
            for (int mt = 0; mt < 4; mt++)
                ldsm4(af[mt][0], af[mt][1], af[mt][2], af[mt][3], kwb + a_woff[mt] * 4);
#pragma unroll
            for (int p = 0; p < 4; p++)
                ldsm4(bf[p][0], bf[p][1], bf[p][2], bf[p][3], kwb + b_woff[p] * 4);
#pragma unroll
            for (int mt = 0; mt < 4; mt++)
#pragma unroll
                for (int nt = 0; nt < 8; nt++)
                    mma_fp16(acc[mt][nt][0], acc[mt][nt][1], acc[mt][nt][2], acc[mt][nt][3],
                             af[mt][0], af[mt][1], af[mt][2], af[mt][3],
                             bf[nt >> 1][(nt & 1) * 2], bf[nt >> 1][(nt & 1) * 2 + 1]);
        }
    }

#pragma unroll
    for (int mt = 0; mt < 4; mt++) {
        const int r = m0 + wm * 64 + mt * 16 + g;
#pragma unroll
        for (int nt = 0; nt < 8; nt++) {
            const int n = n0 + wn * 64 + nt * 8 + 2 * cc;
            *(float2*)&C[(size_t)r * N + n]       = make_float2(acc[mt][nt][0], acc[mt][nt][1]);
            *(float2*)&C[(size_t)(r + 8) * N + n] = make_float2(acc[mt][nt][2], acc[mt][nt][3]);
        }
    }
}

// ---------------- RoPE ----------------
__global__ __launch_bounds__(256) void rope2_kernel(float* __restrict__ proj,
                                                    const int* __restrict__ pos_ids) {
    __shared__ float ca[64], sa[64];
    const int s = blockIdx.x;
    const int t = threadIdx.x;
    if (t < 64) {
        const int pos = pos_ids[s];
        double inv = exp(-((double)t / 64.0) * 9.210340371976184);
        double a = (double)pos * inv;
        const double twopi = 6.283185307179586476925286766559;
        a -= floor(a / twopi) * twopi;
        sa[t] = sinf((float)a);
        ca[t] = cosf((float)a);
    }
    __syncthreads();
    float* base = proj + (size_t)s * P3;
#pragma unroll
    for (int it = 0; it < 16; it++) {
        const int p = t + it * 256;
        const int d = p & 63;
        const int hh = (p >> 6) & 31;
        float* ptr = base + ((p >> 11) ? HID : 0) + hh * HD + d;
        const float x1 = ptr[0], x2 = ptr[64];
        const float c = ca[d], sn = sa[d];
        ptr[0]  = x1 * c - x2 * sn;
        ptr[64] = x2 * c + x1 * sn;
    }
}

// ---------------- bf16-split tensor-core flash attention (unchanged) ----------------
#define QSTR 136
#define VSTR 72
#define SSTR 65
#define OFF_QH  0
#define OFF_QL  (OFF_QH + 128 * QSTR * 2)
#define OFF_KH  (OFF_QL + 128 * QSTR * 2)
#define OFF_KL  (OFF_KH + 64 * QSTR * 2)
#define OFF_VTH (OFF_KL + 64 * QSTR * 2)
#define OFF_VTL (OFF_VTH + 128 * VSTR * 2)
#define OFF_SF  (OFF_VTL + 128 * VSTR * 2)
#define OFF_PH  (OFF_SF + 128 * SSTR * 4)
#define OFF_PL  (OFF_PH + 128 * VSTR * 2)
#define OFF_ST  (OFF_PL + 128 * VSTR * 2)
#define ATTN2_SMEM (OFF_ST + 3 * 128 * 4)

__global__ __launch_bounds__(256, 1) void attn_bf16(const float* __restrict__ proj,
                                                    float* __restrict__ attn_out) {
    extern __shared__ char smraw[];
    uint32_t* Qh  = (uint32_t*)(smraw + OFF_QH);
    uint32_t* Ql  = (uint32_t*)(smraw + OFF_QL);
    uint32_t* Kh  = (uint32_t*)(smraw + OFF_KH);
    uint32_t* Kl  = (uint32_t*)(smraw + OFF_KL);
    uint32_t* Vth = (uint32_t*)(smraw + OFF_VTH);
    uint32_t* Vtl = (uint32_t*)(smraw + OFF_VTL);
    float*    Sf  = (float*)(smraw + OFF_SF);
    uint32_t* Ph  = (uint32_t*)(smraw + OFF_PH);
    uint32_t* Pl  = (uint32_t*)(smraw + OFF_PL);
    float*    rowM = (float*)(smraw + OFF_ST);
    float*    rowL = rowM + 128;
    float*    rowA = rowL + 128;

    const int t = threadIdx.x;
    const int w = t >> 5, lane = t & 31;
    const int g = lane >> 2, cc = lane & 3;
    const int h = blockIdx.x;
    const int qt = 15 - (int)blockIdx.y;
    const int qbase = qt * 128;
    const int qcol = h * HD, kcol = HID + h * HD, vcol = 2 * HID + h * HD;

    {
        const int row = t >> 1;
        const int c0 = (t & 1) * 64;
        const float* src = proj + (size_t)(qbase + row) * P3 + qcol + c0;
        uint32_t* qh = Qh + row * 68 + (c0 >> 1);
        uint32_t* ql = Ql + row * 68 + (c0 >> 1);
#pragma unroll
        for (int i = 0; i < 16; i++) {
            float4 v = *(const float4*)(src + i * 4);
            uint32_t hp, lp;
            split_pair(v.x * NORM, v.y * NORM, hp, lp);
            qh[2 * i] = hp; ql[2 * i] = lp;
            split_pair(v.z * NORM, v.w * NORM, hp, lp);
            qh[2 * i + 1] = hp; ql[2 * i + 1] = lp;
        }
    }
    if (t < 128) { rowM[t] = -3.0e38f; rowL[t] = 0.f; }

    float oacc[16][4];
#pragma unroll
    for (int nt = 0; nt < 16; nt++)
#pragma unroll
        for (int q = 0; q < 4; q++) oacc[nt][q] = 0.f;

    const int nkt = 2 * qt + 2;
    for (int j = 0; j < nkt; j++) {
        __syncthreads();
        {
            const int r = t >> 2;
            const int c0 = (t & 3) * 32;
            const float* src = proj + (size_t)(j * 64 + r) * P3 + kcol + c0;
            uint32_t* kh = Kh + r * 68 + (c0 >> 1);
            uint32_t* kl = Kl + r * 68 + (c0 >> 1);
#pragma unroll
            for (int i = 0; i < 8; i++) {
                float4 v = *(const float4*)(src + i * 4);
                uint32_t hp, lp;
                split_pair(v.x, v.y, hp, lp);
                kh[2 * i] = hp; kl[2 * i] = lp;
                split_pair(v.z, v.w, hp, lp);
                kh[2 * i + 1] = hp; kl[2 * i + 1] = lp;
            }
        }
        {
            const int c = (t & 31) + ((t >> 5) & 3) * 32;
            const int rp0 = (t >> 7) * 16;
            const float* vsrc = proj + (size_t)(j * 64) * P3 + vcol + c;
#pragma unroll
            for (int it = 0; it < 16; it++) {
                const int rp = rp0 + it;
                const float v0 = vsrc[(size_t)(2 * rp) * P3];
                const float v1 = vsrc[(size_t)(2 * rp + 1) * P3];
                uint32_t hp, lp;
                split_pair(v0, v1, hp, lp);
                Vth[c * 36 + rp] = hp;
                Vtl[c * 36 + rp] = lp;
            }
        }
        __syncthreads();

        float sacc[8][4];
#pragma unroll
        for (int nt = 0; nt < 8; nt++)
#pragma unroll
            for (int q = 0; q < 4; q++) sacc[nt][q] = 0.f;

        const uint32_t* q0 = Qh + (w * 16 + g) * 68;
        const uint32_t* q1 = q0 + 8 * 68;
        const uint32_t* q0l = Ql + (w * 16 + g) * 68;
        const uint32_t* q1l = q0l + 8 * 68;
#pragma unroll
        for (int kc = 0; kc < 8; kc++) {
            const int kw = kc * 8;
            uint32_t ah0 = q0[kw + cc], ah1 = q1[kw + cc];
            uint32_t ah2 = q0[kw + cc + 4], ah3 = q1[kw + cc + 4];
            uint32_t al0 = q0l[kw + cc], al1 = q1l[kw + cc];
            uint32_t al2 = q0l[kw + cc + 4], al3 = q1l[kw + cc + 4];
#pragma unroll
            for (int nt = 0; nt < 8; nt++) {
                const int nw = (nt * 8 + g) * 68 + kw;
                uint32_t bh0 = Kh[nw + cc], bh1 = Kh[nw + cc + 4];
                uint32_t bl0 = Kl[nw + cc], bl1 = Kl[nw + cc + 4];
                mma_bf16(sacc[nt][0], sacc[nt][1], sacc[nt][2], sacc[nt][3],
                         ah0, ah1, ah2, ah3, bh0, bh1);
                mma_bf16(sacc[nt][0], sacc[nt][1], sacc[nt][2], sacc[nt][3],
                         ah0, ah1, ah2, ah3, bl0, bl1);
                mma_bf16(sacc[nt][0], sacc[nt][1], sacc[nt][2], sacc[nt][3],
                         al0, al1, al2, al3, bh0, bh1);
            }
        }
        {
            const bool diagt = (j * 64 + 63 > qbase);
            const int r0g = qbase + w * 16 + g;
            float* s0 = Sf + (w * 16 + g) * SSTR;
            float* s1 = s0 + 8 * SSTR;
#pragma unroll
            for (int nt = 0; nt < 8; nt++) {
                const int cg = j * 64 + nt * 8 + 2 * cc;
                float v0 = sacc[nt][0], v1 = sacc[nt][1];
                float v2 = sacc[nt][2], v3 = sacc[nt][3];
                if (diagt) {
                    if (cg     > r0g)     v0 = -1.0e9f;
                    if (cg + 1 > r0g)     v1 = -1.0e9f;
                    if (cg     > r0g + 8) v2 = -1.0e9f;
                    if (cg + 1 > r0g + 8) v3 = -1.0e9f;
                }
                s0[nt * 8 + 2 * cc] = v0; s0[nt * 8 + 2 * cc + 1] = v1;
                s1[nt * 8 + 2 * cc] = v2; s1[nt * 8 + 2 * cc + 1] = v3;
            }
        }
        __syncthreads();

        {
            const int row = t >> 1, half = t & 1;
            const float* pr = Sf + row * SSTR + half * 32;
            float m = -3.0e38f;
#pragma unroll 8
            for (int i = 0; i < 32; i++) m = fmaxf(m, pr[i]);
            m = fmaxf(m, __shfl_xor_sync(0xFFFFFFFFu, m, 1));
            const float mold = rowM[row];
            const float mnew = fmaxf(mold, m);
            float ssum = 0.f;
            uint32_t* ph = Ph + row * 36 + half * 16;
            uint32_t* pl = Pl + row * 36 + half * 16;
#pragma unroll 4
            for (int i = 0; i < 16; i++) {
                const float p0 = __expf(pr[2 * i] - mnew);
                const float p1 = __expf(pr[2 * i + 1] - mnew);
                ssum += p0 + p1;
                uint32_t hp, lp;
                split_pair(p0, p1, hp, lp);
                ph[i] = hp; pl[i] = lp;
            }
            ssum += __shfl_xor_sync(0xFFFFFFFFu, ssum, 1);
            if (half == 0) {
                const float alpha = __expf(mold - mnew);
                rowA[row] = alpha;
                rowL[row] = rowL[row] * alpha + ssum;
                rowM[row] = mnew;
            }
        }
        __syncthreads();

        {
            const float al0 = rowA[w * 16 + g], al1 = rowA[w * 16 + 8 + g];
#pragma unroll
            for (int nt = 0; nt < 16; nt++) {
                oacc[nt][0] *= al0; oacc[nt][1] *= al0;
                oacc[nt][2] *= al1; oacc[nt][3] *= al1;
            }
            const uint32_t* p0 = Ph + (w * 16 + g) * 36;
            const uint32_t* p1 = p0 + 8 * 36;
            const uint32_t* p0l = Pl + (w * 16 + g) * 36;
            const uint32_t* p1l = p0l + 8 * 36;
#pragma unroll
            for (int kc = 0; kc < 4; kc++) {
                const int kw = kc * 8;
                uint32_t ah0 = p0[kw + cc], ah1 = p1[kw + cc];
                uint32_t ah2 = p0[kw + cc + 4], ah3 = p1[kw + cc + 4];
                uint32_t al0f = p0l[kw + cc], al1f = p1l[kw + cc];
                uint32_t al2f = p0l[kw + cc + 4], al3f = p1l[kw + cc + 4];
#pragma unroll
                for (int nt = 0; nt < 16; nt++) {
                    const int nw = (nt * 8 + g) * 36 + kw;
                    uint32_t bh0 = Vth[nw + cc], bh1 = Vth[nw + cc + 4];
                    uint32_t bl0 = Vtl[nw + cc], bl1 = Vtl[nw + cc + 4];
                    mma_bf16(oacc[nt][0], oacc[nt][1], oacc[nt][2], oacc[nt][3],
                             ah0, ah1, ah2, ah3, bh0, bh1);
                    mma_bf16(oacc[nt][0], oacc[nt][1], oacc[nt][2], oacc[nt][3],
                             ah0, ah1, ah2, ah3, bl0, bl1);
                    mma_bf16(oacc[nt][0], oacc[nt][1], oacc[nt][2], oacc[nt][3],
                             al0f, al1f, al2f, al3f, bh0, bh1);
                }
            }
        }
    }

    {
        const float il0 = 1.0f / rowL[w * 16 + g];
        const float il1 = 1.0f / rowL[w * 16 + 8 + g];
        const size_t base0 = (size_t)(qbase + w * 16 + g) * HID + h * HD + 2 * cc;
#pragma unroll
        for (int nt = 0; nt < 16; nt++) {
            *(float2*)(attn_out + base0 + nt * 8) =
                make_float2(oacc[nt][0] * il0, oacc[nt][1] * il0);
            *(float2*)(attn_out + base0 + 8 * HID + nt * 8) =
                make_float2(oacc[nt][2] * il1, oacc[nt][3] * il1);
        }
    }
}

// ---------------- launch ----------------
extern "C" void kernel_launch(void* const* d_in, const int* in_sizes, int n_in,
                              void* d_out, int out_size) {
    (void)in_sizes; (void)n_in; (void)out_size;
    const float* hidden  = (const float*)d_in[0];
    const int*   pos_ids = (const int*)d_in[2];
    const float* W_pack  = (const float*)d_in[3];
    const float* W_o     = (const float*)d_in[4];
    float* out = (float*)d_out;

    float *proj = nullptr, *attn = nullptr;
    __half *hid_h = nullptr, *wp_h = nullptr, *wo_h = nullptr, *attn_h = nullptr;
    cudaGetSymbolAddress((void**)&proj, g_proj);
    cudaGetSymbolAddress((void**)&attn, g_attn);
    cudaGetSymbolAddress((void**)&hid_h, g_hid_h);
    cudaGetSymbolAddress((void**)&wp_h, g_wp_h);
    cudaGetSymbolAddress((void**)&wo_h, g_wo_h);
    cudaGetSymbolAddress((void**)&attn_h, g_attn_h);
    cudaFuncSetAttribute(attn_bf16, cudaFuncAttributeMaxDynamicSharedMemorySize, ATTN2_SMEM);
    cudaFuncSetAttribute(gemm_fp16ca, cudaFuncAttributeMaxDynamicSharedMemorySize, GEMM_SMEM);

    // converts (bandwidth-bound)
    f2h_kernel<<<(S_LEN * HID) / (256 * 8), 256>>>(hidden, hid_h, S_LEN * HID);
    f2h_kernel<<<(P3 * HID) / (256 * 8), 256>>>(W_pack, wp_h, P3 * HID);
    f2h_kernel<<<(HID * HID) / (256 * 8), 256>>>(W_o, wo_h, HID * HID);

    // 1) QKV projection (fp16 cp.async + ldmatrix, BK=64)
    gemm_fp16ca<<<dim3(P3 / 256, S_LEN / 128), 256, GEMM_SMEM>>>(hid_h, wp_h, proj,
                                                                 S_LEN, P3, HID);
    // 2) RoPE in-place on Q,K
    rope2_kernel<<<S_LEN, 256>>>(proj, pos_ids);
    // 3) causal flash attention (bf16-split tensor cores)
    attn_bf16<<<dim3(NH, S_LEN / 128), 256, ATTN2_SMEM>>>(proj, attn);
    // 4) output projection
    f2h_kernel<<<(S_LEN * HID) / (256 * 8), 256>>>(attn, attn_h, S_LEN * HID);
    gemm_fp16ca<<<dim3(HID / 256, S_LEN / 128), 256, GEMM_SMEM>>>(attn_h, wo_h, out,
                                                                  S_LEN, HID, HID);
}

// round 13
// speedup vs baseline: 1.0382x; 1.0382x over previous
#include <cuda_runtime.h>
#include <cuda_fp16.h>
#include <cstdint>
#include <cstddef>

#define S_LEN 2048
#define HID   4096
#define NH    32
#define HD    128
#define P3    12288   // 3*HID
#define NORM  0.08838834764831845f   // 1/sqrt(128)

// ---------------- scratch (no allocations allowed) ----------------
__device__ float  g_proj[S_LEN * P3];
__device__ float  g_attn[S_LEN * HID];
__device__ __half g_hid_h[S_LEN * HID];
__device__ __half g_wp_h[P3 * HID];
__device__ __half g_wo_h[HID * HID];
__device__ __half g_attn_h[S_LEN * HID];

// ---------------- helpers ----------------
__device__ __forceinline__ uint32_t smem_u32(const void* p) {
    uint32_t a;
    asm("{ .reg .u64 t; cvta.to.shared.u64 t, %1; cvt.u32.u64 %0, t; }" : "=r"(a) : "l"(p));
    return a;
}
__device__ __forceinline__ void cp16(uint32_t saddr, const void* gptr) {
    asm volatile("cp.async.ca.shared.global [%0], [%1], 16;" :: "r"(saddr), "l"(gptr));
}
#define CP_COMMIT() asm volatile("cp.async.commit_group;" ::: "memory")
#define CP_WAIT(n)  asm volatile("cp.async.wait_group %0;" :: "n"(n) : "memory")

__device__ __forceinline__ void ldsm4(uint32_t& r0, uint32_t& r1, uint32_t& r2, uint32_t& r3,
                                      uint32_t addr) {
    asm volatile("ldmatrix.sync.aligned.m8n8.x4.shared.b16 {%0,%1,%2,%3}, [%4];"
                 : "=r"(r0), "=r"(r1), "=r"(r2), "=r"(r3) : "r"(addr));
}

// mma.sync m16n8k16 fp16, fp32 accum
__device__ __forceinline__ void mma_fp16(float& c0, float& c1, float& c2, float& c3,
                                         uint32_t a0, uint32_t a1, uint32_t a2, uint32_t a3,
                                         uint32_t b0, uint32_t b1) {
    asm volatile(
        "mma.sync.aligned.m16n8k16.row.col.f32.f16.f16.f32 "
        "{%0,%1,%2,%3}, {%4,%5,%6,%7}, {%8,%9}, {%0,%1,%2,%3};"
        : "+f"(c0), "+f"(c1), "+f"(c2), "+f"(c3)
        : "r"(a0), "r"(a1), "r"(a2), "r"(a3), "r"(b0), "r"(b1));
}
// mma.sync m16n8k16 bf16 (attention)
__device__ __forceinline__ void mma_bf16(float& c0, float& c1, float& c2, float& c3,
                                         uint32_t a0, uint32_t a1, uint32_t a2, uint32_t a3,
                                         uint32_t b0, uint32_t b1) {
    asm volatile(
        "mma.sync.aligned.m16n8k16.row.col.f32.bf16.bf16.f32 "
        "{%0,%1,%2,%3}, {%4,%5,%6,%7}, {%8,%9}, {%0,%1,%2,%3};"
        : "+f"(c0), "+f"(c1), "+f"(c2), "+f"(c3)
        : "r"(a0), "r"(a1), "r"(a2), "r"(a3), "r"(b0), "r"(b1));
}
__device__ __forceinline__ void split_pair(float x0, float x1, uint32_t& hp, uint32_t& lp) {
    uint16_t h0, h1, l0, l1;
    asm("cvt.rn.bf16.f32 %0, %1;" : "=h"(h0) : "f"(x0));
    asm("cvt.rn.bf16.f32 %0, %1;" : "=h"(h1) : "f"(x1));
    float r0 = x0 - __uint_as_float((uint32_t)h0 << 16);
    float r1 = x1 - __uint_as_float((uint32_t)h1 << 16);
    asm("cvt.rn.bf16.f32 %0, %1;" : "=h"(l0) : "f"(r0));
    asm("cvt.rn.bf16.f32 %0, %1;" : "=h"(l1) : "f"(r1));
    asm("mov.b32 %0, {%1, %2};" : "=r"(hp) : "h"(h0), "h"(h1));
    asm("mov.b32 %0, {%1, %2};" : "=r"(lp) : "h"(l0), "h"(l1));
}

// ---------------- fp32 -> fp16 convert ----------------
__global__ __launch_bounds__(256) void f2h_kernel(const float* __restrict__ src,
                                                  __half* __restrict__ dst, int n) {
    int i = (blockIdx.x * blockDim.x + threadIdx.x) * 8;
    if (i >= n) return;
    float4 a = *(const float4*)(src + i);
    float4 b = *(const float4*)(src + i + 4);
    __half2 h0 = __floats2half2_rn(a.x, a.y);
    __half2 h1 = __floats2half2_rn(a.z, a.w);
    __half2 h2 = __floats2half2_rn(b.x, b.y);
    __half2 h3 = __floats2half2_rn(b.z, b.w);
    uint4 v = {*(uint32_t*)&h0, *(uint32_t*)&h1, *(uint32_t*)&h2, *(uint32_t*)&h3};
    *(uint4*)(dst + i) = v;
}

// ---------------- fp16 cp.async + ldmatrix GEMM: C = A * B^T ----------------
// Block 128x256x32, 256 threads (8 warps 2x4), warp tile 64x64.
// R10 layout (KW=20, verified conflict-free) + 6-stage ring, 2 stages per barrier.
#define KW    20
#define NSTG  6
#define AW    (128 * KW)                       // A words per stage
#define STGW  ((128 + 256) * KW)               // 7680 words per stage
#define GEMM_SMEM (NSTG * STGW * 4)            // 184320 B

__global__ __launch_bounds__(256, 1) void gemm_fp16ca(const __half* __restrict__ A,
                                                      const __half* __restrict__ B,
                                                      float* __restrict__ C,
                                                      int M, int N, int K) {
    extern __shared__ uint32_t sm[];
    const int t = threadIdx.x;
    const int w = t >> 5, lane = t & 31;
    const int wm = w >> 2, wn = w & 3;         // 2x4 warp grid, warp tile 64x64
    const int g = lane >> 2, cc = lane & 3;
    const int m0 = blockIdx.y * 128, n0 = blockIdx.x * 256;
    const int KT = K >> 5;
    const uint32_t sbase = smem_u32(sm);

    // cp.async: A 512 chunks (2/thread, same row), B 1024 chunks (4/thread, rows +64j)
    const int ar = t >> 1, ac = (t & 1) * 2;
    const __half* AgA = A + (size_t)(m0 + ar) * K + ac * 8;
    const uint32_t saA = sbase + (ar * KW + ac * 4) * 4;
    const int br = t >> 2, bc = t & 3;
    const __half* BgB = B + (size_t)(n0 + br) * K + bc * 8;
    const uint32_t saB = sbase + AW * 4 + (br * KW + bc * 4) * 4;

    // ldmatrix per-lane word offsets (within stage)
    const int lrow = lane & 7, sel = lane >> 3;
    uint32_t a_woff[4], b_woff[4];
#pragma unroll
    for (int mt = 0; mt < 4; mt++)
        a_woff[mt] = (uint32_t)((wm * 64 + mt * 16 + lrow + (sel & 1) * 8) * KW +
                                (sel >> 1) * 4);
#pragma unroll
    for (int p = 0; p < 4; p++)
        b_woff[p] = (uint32_t)(AW + (wn * 64 + p * 16 + (sel >> 1) * 8 + lrow) * KW +
                               (sel & 1) * 4);

    // prologue: stages 0..3 (4 groups)
#pragma unroll
    for (int s = 0; s < 4; s++) {
        const uint32_t so = s * STGW * 4;
        const size_t ko = (size_t)s * 32;
        cp16(saA + so, AgA + ko);
        cp16(saA + so + 16, AgA + ko + 8);
#pragma unroll
        for (int j = 0; j < 4; j++)
            cp16(saB + so + j * (64 * KW * 4), BgB + (size_t)(64 * j) * K + ko);
        CP_COMMIT();
    }

    float acc[4][8][4];
#pragma unroll
    for (int mt = 0; mt < 4; mt++)
#pragma unroll
        for (int nt = 0; nt < 8; nt++)
#pragma unroll
            for (int q = 0; q < 4; q++) acc[mt][nt][q] = 0.f;

    for (int kt = 0; kt < KT; kt += 2) {
        CP_WAIT(2);          // stages kt, kt+1 complete (kt+2, kt+3 may be pending)
        __syncthreads();
        // prefetch stages kt+4, kt+5 (one commit group each)
#pragma unroll
        for (int s = 0; s < 2; s++) {
            const int pf = kt + 4 + s;
            if (pf < KT) {
                const uint32_t so = (pf % NSTG) * STGW * 4;
                const size_t ko = (size_t)pf * 32;
                cp16(saA + so, AgA + ko);
                cp16(saA + so + 16, AgA + ko + 8);
#pragma unroll
                for (int j = 0; j < 4; j++)
                    cp16(saB + so + j * (64 * KW * 4), BgB + (size_t)(64 * j) * K + ko);
            }
            CP_COMMIT();
        }
        // compute stages kt, kt+1
#pragma unroll
        for (int s2 = 0; s2 < 2; s2++) {
            const uint32_t stgoff = sbase + (((kt + s2) % NSTG) * STGW) * 4;
#pragma unroll
            for (int hh = 0; hh < 2; hh++) {
                const uint32_t kwb = stgoff + hh * 8 * 4;
                uint32_t af[4][4], bf[4][4];
#pragma unroll
                for (int mt = 0; mt < 4; mt++)
                    ldsm4(af[mt][0], af[mt][1], af[mt][2], af[mt][3], kwb + a_woff[mt] * 4);
#pragma unroll
                for (int p = 0; p < 4; p++)
                    ldsm4(bf[p][0], bf[p][1], bf[p][2], bf[p][3], kwb + b_woff[p] * 4);
#pragma unroll
                for (int mt = 0; mt < 4; mt++)
#pragma unroll
                    for (int nt = 0; nt < 8; nt++)
                        mma_fp16(acc[mt][nt][0], acc[mt][nt][1], acc[mt][nt][2], acc[mt][nt][3],
                                 af[mt][0], af[mt][1], af[mt][2], af[mt][3],
                                 bf[nt >> 1][(nt & 1) * 2], bf[nt >> 1][(nt & 1) * 2 + 1]);
            }
        }
    }

#pragma unroll
    for (int mt = 0; mt < 4; mt++) {
        const int r = m0 + wm * 64 + mt * 16 + g;
#pragma unroll
        for (int nt = 0; nt < 8; nt++) {
            const int n = n0 + wn * 64 + nt * 8 + 2 * cc;
            *(float2*)&C[(size_t)r * N + n]       = make_float2(acc[mt][nt][0], acc[mt][nt][1]);
            *(float2*)&C[(size_t)(r + 8) * N + n] = make_float2(acc[mt][nt][2], acc[mt][nt][3]);
        }
    }
}

// ---------------- RoPE ----------------
__global__ __launch_bounds__(256) void rope2_kernel(float* __restrict__ proj,
                                                    const int* __restrict__ pos_ids) {
    __shared__ float ca[64], sa[64];
    const int s = blockIdx.x;
    const int t = threadIdx.x;
    if (t < 64) {
        const int pos = pos_ids[s];
        double inv = exp(-((double)t / 64.0) * 9.210340371976184);
        double a = (double)pos * inv;
        const double twopi = 6.283185307179586476925286766559;
        a -= floor(a / twopi) * twopi;
        sa[t] = sinf((float)a);
        ca[t] = cosf((float)a);
    }
    __syncthreads();
    float* base = proj + (size_t)s * P3;
#pragma unroll
    for (int it = 0; it < 16; it++) {
        const int p = t + it * 256;
        const int d = p & 63;
        const int hh = (p >> 6) & 31;
        float* ptr = base + ((p >> 11) ? HID : 0) + hh * HD + d;
        const float x1 = ptr[0], x2 = ptr[64];
        const float c = ca[d], sn = sa[d];
        ptr[0]  = x1 * c - x2 * sn;
        ptr[64] = x2 * c + x1 * sn;
    }
}

// ---------------- bf16-split tensor-core flash attention (unchanged) ----------------
#define QSTR 136
#define VSTR 72
#define SSTR 65
#define OFF_QH  0
#define OFF_QL  (OFF_QH + 128 * QSTR * 2)
#define OFF_KH  (OFF_QL + 128 * QSTR * 2)
#define OFF_KL  (OFF_KH + 64 * QSTR * 2)
#define OFF_VTH (OFF_KL + 64 * QSTR * 2)
#define OFF_VTL (OFF_VTH + 128 * VSTR * 2)
#define OFF_SF  (OFF_VTL + 128 * VSTR * 2)
#define OFF_PH  (OFF_SF + 128 * SSTR * 4)
#define OFF_PL  (OFF_PH + 128 * VSTR * 2)
#define OFF_ST  (OFF_PL + 128 * VSTR * 2)
#define ATTN2_SMEM (OFF_ST + 3 * 128 * 4)

__global__ __launch_bounds__(256, 1) void attn_bf16(const float* __restrict__ proj,
                                                    float* __restrict__ attn_out) {
    extern __shared__ char smraw[];
    uint32_t* Qh  = (uint32_t*)(smraw + OFF_QH);
    uint32_t* Ql  = (uint32_t*)(smraw + OFF_QL);
    uint32_t* Kh  = (uint32_t*)(smraw + OFF_KH);
    uint32_t* Kl  = (uint32_t*)(smraw + OFF_KL);
    uint32_t* Vth = (uint32_t*)(smraw + OFF_VTH);
    uint32_t* Vtl = (uint32_t*)(smraw + OFF_VTL);
    float*    Sf  = (float*)(smraw + OFF_SF);
    uint32_t* Ph  = (uint32_t*)(smraw + OFF_PH);
    uint32_t* Pl  = (uint32_t*)(smraw + OFF_PL);
    float*    rowM = (float*)(smraw + OFF_ST);
    float*    rowL = rowM + 128;
    float*    rowA = rowL + 128;

    const int t = threadIdx.x;
    const int w = t >> 5, lane = t & 31;
    const int g = lane >> 2, cc = lane & 3;
    const int h = blockIdx.x;
    const int qt = 15 - (int)blockIdx.y;
    const int qbase = qt * 128;
    const int qcol = h * HD, kcol = HID + h * HD, vcol = 2 * HID + h * HD;

    {
        const int row = t >> 1;
        const int c0 = (t & 1) * 64;
        const float* src = proj + (size_t)(qbase + row) * P3 + qcol + c0;
        uint32_t* qh = Qh + row * 68 + (c0 >> 1);
        uint32_t* ql = Ql + row * 68 + (c0 >> 1);
#pragma unroll
        for (int i = 0; i < 16; i++) {
            float4 v = *(const float4*)(src + i * 4);
            uint32_t hp, lp;
            split_pair(v.x * NORM, v.y * NORM, hp, lp);
            qh[2 * i] = hp; ql[2 * i] = lp;
            split_pair(v.z * NORM, v.w * NORM, hp, lp);
            qh[2 * i + 1] = hp; ql[2 * i + 1] = lp;
        }
    }
    if (t < 128) { rowM[t] = -3.0e38f; rowL[t] = 0.f; }

    float oacc[16][4];
#pragma unroll
    for (int nt = 0; nt < 16; nt++)
#pragma unroll
        for (int q = 0; q < 4; q++) oacc[nt][q] = 0.f;

    const int nkt = 2 * qt + 2;
    for (int j = 0; j < nkt; j++) {
        __syncthreads();
        {
            const int r = t >> 2;
            const int c0 = (t & 3) * 32;
            const float* src = proj + (size_t)(j * 64 + r) * P3 + kcol + c0;
            uint32_t* kh = Kh + r * 68 + (c0 >> 1);
            uint32_t* kl = Kl + r * 68 + (c0 >> 1);
#pragma unroll
            for (int i = 0; i < 8; i++) {
                float4 v = *(const float4*)(src + i * 4);
                uint32_t hp, lp;
                split_pair(v.x, v.y, hp, lp);
                kh[2 * i] = hp; kl[2 * i] = lp;
                split_pair(v.z, v.w, hp, lp);
                kh[2 * i + 1] = hp; kl[2 * i + 1] = lp;
            }
        }
        {
            const int c = (t & 31) + ((t >> 5) & 3) * 32;
            const int rp0 = (t >> 7) * 16;
            const float* vsrc = proj + (size_t)(j * 64) * P3 + vcol + c;
#pragma unroll
            for (int it = 0; it < 16; it++) {
                const int rp = rp0 + it;
                const float v0 = vsrc[(size_t)(2 * rp) * P3];
                const float v1 = vsrc[(size_t)(2 * rp + 1) * P3];
                uint32_t hp, lp;
                split_pair(v0, v1, hp, lp);
                Vth[c * 36 + rp] = hp;
                Vtl[c * 36 + rp] = lp;
            }
        }
        __syncthreads();

        float sacc[8][4];
#pragma unroll
        for (int nt = 0; nt < 8; nt++)
#pragma unroll
            for (int q = 0; q < 4; q++) sacc[nt][q] = 0.f;

        const uint32_t* q0 = Qh + (w * 16 + g) * 68;
        const uint32_t* q1 = q0 + 8 * 68;
        const uint32_t* q0l = Ql + (w * 16 + g) * 68;
        const uint32_t* q1l = q0l + 8 * 68;
#pragma unroll
        for (int kc = 0; kc < 8; kc++) {
            const int kw = kc * 8;
            uint32_t ah0 = q0[kw + cc], ah1 = q1[kw + cc];
            uint32_t ah2 = q0[kw + cc + 4], ah3 = q1[kw + cc + 4];
            uint32_t al0 = q0l[kw + cc], al1 = q1l[kw + cc];
            uint32_t al2 = q0l[kw + cc + 4], al3 = q1l[kw + cc + 4];
#pragma unroll
            for (int nt = 0; nt < 8; nt++) {
                const int nw = (nt * 8 + g) * 68 + kw;
                uint32_t bh0 = Kh[nw + cc], bh1 = Kh[nw + cc + 4];
                uint32_t bl0 = Kl[nw + cc], bl1 = Kl[nw + cc + 4];
                mma_bf16(sacc[nt][0], sacc[nt][1], sacc[nt][2], sacc[nt][3],
                         ah0, ah1, ah2, ah3, bh0, bh1);
                mma_bf16(sacc[nt][0], sacc[nt][1], sacc[nt][2], sacc[nt][3],
                         ah0, ah1, ah2, ah3, bl0, bl1);
                mma_bf16(sacc[nt][0], sacc[nt][1], sacc[nt][2], sacc[nt][3],
                         al0, al1, al2, al3, bh0, bh1);
            }
        }
        {
            const bool diagt = (j * 64 + 63 > qbase);
            const int r0g = qbase + w * 16 + g;
            float* s0 = Sf + (w * 16 + g) * SSTR;
            float* s1 = s0 + 8 * SSTR;
#pragma unroll
            for (int nt = 0; nt < 8; nt++) {
                const int cg = j * 64 + nt * 8 + 2 * cc;
                float v0 = sacc[nt][0], v1 = sacc[nt][1];
                float v2 = sacc[nt][2], v3 = sacc[nt][3];
                if (diagt) {
                    if (cg     > r0g)     v0 = -1.0e9f;
                    if (cg + 1 > r0g)     v1 = -1.0e9f;
                    if (cg     > r0g + 8) v2 = -1.0e9f;
                    if (cg + 1 > r0g + 8) v3 = -1.0e9f;
                }
                s0[nt * 8 + 2 * cc] = v0; s0[nt * 8 + 2 * cc + 1] = v1;
                s1[nt * 8 + 2 * cc] = v2; s1[nt * 8 + 2 * cc + 1] = v3;
            }
        }
        __syncthreads();

        {
            const int row = t >> 1, half = t & 1;
            const float* pr = Sf + row * SSTR + half * 32;
            float m = -3.0e38f;
#pragma unroll 8
            for (int i = 0; i < 32; i++) m = fmaxf(m, pr[i]);
            m = fmaxf(m, __shfl_xor_sync(0xFFFFFFFFu, m, 1));
            const float mold = rowM[row];
            const float mnew = fmaxf(mold, m);
            float ssum = 0.f;
            uint32_t* ph = Ph + row * 36 + half * 16;
            uint32_t* pl = Pl + row * 36 + half * 16;
#pragma unroll 4
            for (int i = 0; i < 16; i++) {
                const float p0 = __expf(pr[2 * i] - mnew);
                const float p1 = __expf(pr[2 * i + 1] - mnew);
                ssum += p0 + p1;
                uint32_t hp, lp;
                split_pair(p0, p1, hp, lp);
                ph[i] = hp; pl[i] = lp;
            }
            ssum += __shfl_xor_sync(0xFFFFFFFFu, ssum, 1);
            if (half == 0) {
                const float alpha = __expf(mold - mnew);
                rowA[row] = alpha;
                rowL[row] = rowL[row] * alpha + ssum;
                rowM[row] = mnew;
            }
        }
        __syncthreads();

        {
            const float al0 = rowA[w * 16 + g], al1 = rowA[w * 16 + 8 + g];
#pragma unroll
            for (int nt = 0; nt < 16; nt++) {
                oacc[nt][0] *= al0; oacc[nt][1] *= al0;
                oacc[nt][2] *= al1; oacc[nt][3] *= al1;
            }
            const uint32_t* p0 = Ph + (w * 16 + g) * 36;
            const uint32_t* p1 = p0 + 8 * 36;
            const uint32_t* p0l = Pl + (w * 16 + g) * 36;
            const uint32_t* p1l = p0l + 8 * 36;
#pragma unroll
            for (int kc = 0; kc < 4; kc++) {
                const int kw = kc * 8;
                uint32_t ah0 = p0[kw + cc], ah1 = p1[kw + cc];
                uint32_t ah2 = p0[kw + cc + 4], ah3 = p1[kw + cc + 4];
                uint32_t al0f = p0l[kw + cc], al1f = p1l[kw + cc];
                uint32_t al2f = p0l[kw + cc + 4], al3f = p1l[kw + cc + 4];
#pragma unroll
                for (int nt = 0; nt < 16; nt++) {
                    const int nw = (nt * 8 + g) * 36 + kw;
                    uint32_t bh0 = Vth[nw + cc], bh1 = Vth[nw + cc + 4];
                    uint32_t bl0 = Vtl[nw + cc], bl1 = Vtl[nw + cc + 4];
                    mma_bf16(oacc[nt][0], oacc[nt][1], oacc[nt][2], oacc[nt][3],
                             ah0, ah1, ah2, ah3, bh0, bh1);
                    mma_bf16(oacc[nt][0], oacc[nt][1], oacc[nt][2], oacc[nt][3],
                             ah0, ah1, ah2, ah3, bl0, bl1);
                    mma_bf16(oacc[nt][0], oacc[nt][1], oacc[nt][2], oacc[nt][3],
                             al0f, al1f, al2f, al3f, bh0, bh1);
                }
            }
        }
    }

    {
        const float il0 = 1.0f / rowL[w * 16 + g];
        const float il1 = 1.0f / rowL[w * 16 + 8 + g];
        const size_t base0 = (size_t)(qbase + w * 16 + g) * HID + h * HD + 2 * cc;
#pragma unroll
        for (int nt = 0; nt < 16; nt++) {
            *(float2*)(attn_out + base0 + nt * 8) =
                make_float2(oacc[nt][0] * il0, oacc[nt][1] * il0);
            *(float2*)(attn_out + base0 + 8 * HID + nt * 8) =
                make_float2(oacc[nt][2] * il1, oacc[nt][3] * il1);
        }
    }
}

// ---------------- launch ----------------
extern "C" void kernel_launch(void* const* d_in, const int* in_sizes, int n_in,
                              void* d_out, int out_size) {
    (void)in_sizes; (void)n_in; (void)out_size;
    const float* hidden  = (const float*)d_in[0];
    const int*   pos_ids = (const int*)d_in[2];
    const float* W_pack  = (const float*)d_in[3];
    const float* W_o     = (const float*)d_in[4];
    float* out = (float*)d_out;

    float *proj = nullptr, *attn = nullptr;
    __half *hid_h = nullptr, *wp_h = nullptr, *wo_h = nullptr, *attn_h = nullptr;
    cudaGetSymbolAddress((void**)&proj, g_proj);
    cudaGetSymbolAddress((void**)&attn, g_attn);
    cudaGetSymbolAddress((void**)&hid_h, g_hid_h);
    cudaGetSymbolAddress((void**)&wp_h, g_wp_h);
    cudaGetSymbolAddress((void**)&wo_h, g_wo_h);
    cudaGetSymbolAddress((void**)&attn_h, g_attn_h);
    cudaFuncSetAttribute(attn_bf16, cudaFuncAttributeMaxDynamicSharedMemorySize, ATTN2_SMEM);
    cudaFuncSetAttribute(gemm_fp16ca, cudaFuncAttributeMaxDynamicSharedMemorySize, GEMM_SMEM);

    // converts (bandwidth-bound)
    f2h_kernel<<<(S_LEN * HID) / (256 * 8), 256>>>(hidden, hid_h, S_LEN * HID);
    f2h_kernel<<<(P3 * HID) / (256 * 8), 256>>>(W_pack, wp_h, P3 * HID);
    f2h_kernel<<<(HID * HID) / (256 * 8), 256>>>(W_o, wo_h, HID * HID);

    // 1) QKV projection (fp16 cp.async + ldmatrix, 2 stages per barrier)
    gemm_fp16ca<<<dim3(P3 / 256, S_LEN / 128), 256, GEMM_SMEM>>>(hid_h, wp_h, proj,
                                                                 S_LEN, P3, HID);
    // 2) RoPE in-place on Q,K
    rope2_kernel<<<S_LEN, 256>>>(proj, pos_ids);
    // 3) causal flash attention (bf16-split tensor cores)
    attn_bf16<<<dim3(NH, S_LEN / 128), 256, ATTN2_SMEM>>>(proj, attn);
    // 4) output projection
    f2h_kernel<<<(S_LEN * HID) / (256 * 8), 256>>>(attn, attn_h, S_LEN * HID);
    gemm_fp16ca<<<dim3(HID / 256, S_LEN / 128), 256, GEMM_SMEM>>>(attn_h, wo_h, out,
                                                                  S_LEN, HID, HID);
}

// round 14
// speedup vs baseline: 1.1699x; 1.1268x over previous
#include <cuda_runtime.h>
#include <cuda_fp16.h>
#include <cstdint>
#include <cstddef>

#define S_LEN 2048
#define HID   4096
#define NH    32
#define HD    128
#define P3    12288   // 3*HID
#define NORM  0.08838834764831845f   // 1/sqrt(128)

// ---------------- scratch (no allocations allowed) ----------------
__device__ float  g_proj[S_LEN * P3];
__device__ float  g_attn[S_LEN * HID];
__device__ __half g_hid_h[S_LEN * HID];
__device__ __half g_wp_h[P3 * HID];
__device__ __half g_wo_h[HID * HID];
__device__ __half g_attn_h[S_LEN * HID];

// ---------------- helpers ----------------
__device__ __forceinline__ uint32_t smem_u32(const void* p) {
    uint32_t a;
    asm("{ .reg .u64 t; cvta.to.shared.u64 t, %1; cvt.u32.u64 %0, t; }" : "=r"(a) : "l"(p));
    return a;
}
__device__ __forceinline__ void cp16(uint32_t saddr, const void* gptr) {
    asm volatile("cp.async.ca.shared.global [%0], [%1], 16;" :: "r"(saddr), "l"(gptr));
}
#define CP_COMMIT() asm volatile("cp.async.commit_group;" ::: "memory")
#define CP_WAIT(n)  asm volatile("cp.async.wait_group %0;" :: "n"(n) : "memory")

__device__ __forceinline__ void ldsm4(uint32_t& r0, uint32_t& r1, uint32_t& r2, uint32_t& r3,
                                      uint32_t addr) {
    asm volatile("ldmatrix.sync.aligned.m8n8.x4.shared.b16 {%0,%1,%2,%3}, [%4];"
                 : "=r"(r0), "=r"(r1), "=r"(r2), "=r"(r3) : "r"(addr));
}

// mma.sync m16n8k16 fp16, fp32 accum
__device__ __forceinline__ void mma_fp16(float& c0, float& c1, float& c2, float& c3,
                                         uint32_t a0, uint32_t a1, uint32_t a2, uint32_t a3,
                                         uint32_t b0, uint32_t b1) {
    asm volatile(
        "mma.sync.aligned.m16n8k16.row.col.f32.f16.f16.f32 "
        "{%0,%1,%2,%3}, {%4,%5,%6,%7}, {%8,%9}, {%0,%1,%2,%3};"
        : "+f"(c0), "+f"(c1), "+f"(c2), "+f"(c3)
        : "r"(a0), "r"(a1), "r"(a2), "r"(a3), "r"(b0), "r"(b1));
}
// mma.sync m16n8k16 bf16 (attention)
__device__ __forceinline__ void mma_bf16(float& c0, float& c1, float& c2, float& c3,
                                         uint32_t a0, uint32_t a1, uint32_t a2, uint32_t a3,
                                         uint32_t b0, uint32_t b1) {
    asm volatile(
        "mma.sync.aligned.m16n8k16.row.col.f32.bf16.bf16.f32 "
        "{%0,%1,%2,%3}, {%4,%5,%6,%7}, {%8,%9}, {%0,%1,%2,%3};"
        : "+f"(c0), "+f"(c1), "+f"(c2), "+f"(c3)
        : "r"(a0), "r"(a1), "r"(a2), "r"(a3), "r"(b0), "r"(b1));
}
__device__ __forceinline__ void split_pair(float x0, float x1, uint32_t& hp, uint32_t& lp) {
    uint16_t h0, h1, l0, l1;
    asm("cvt.rn.bf16.f32 %0, %1;" : "=h"(h0) : "f"(x0));
    asm("cvt.rn.bf16.f32 %0, %1;" : "=h"(h1) : "f"(x1));
    float r0 = x0 - __uint_as_float((uint32_t)h0 << 16);
    float r1 = x1 - __uint_as_float((uint32_t)h1 << 16);
    asm("cvt.rn.bf16.f32 %0, %1;" : "=h"(l0) : "f"(r0));
    asm("cvt.rn.bf16.f32 %0, %1;" : "=h"(l1) : "f"(r1));
    asm("mov.b32 %0, {%1, %2};" : "=r"(hp) : "h"(h0), "h"(h1));
    asm("mov.b32 %0, {%1, %2};" : "=r"(lp) : "h"(l0), "h"(l1));
}

// ---------------- fp32 -> fp16 convert ----------------
__global__ __launch_bounds__(256) void f2h_kernel(const float* __restrict__ src,
                                                  __half* __restrict__ dst, int n) {
    int i = (blockIdx.x * blockDim.x + threadIdx.x) * 8;
    if (i >= n) return;
    float4 a = *(const float4*)(src + i);
    float4 b = *(const float4*)(src + i + 4);
    __half2 h0 = __floats2half2_rn(a.x, a.y);
    __half2 h1 = __floats2half2_rn(a.z, a.w);
    __half2 h2 = __floats2half2_rn(b.x, b.y);
    __half2 h3 = __floats2half2_rn(b.z, b.w);
    uint4 v = {*(uint32_t*)&h0, *(uint32_t*)&h1, *(uint32_t*)&h2, *(uint32_t*)&h3};
    *(uint4*)(dst + i) = v;
}

// ---------------- fp16 cp.async + ldmatrix GEMM: C = A * B^T ----------------
// Block 128x256x32, 256 threads (8 warps 2x4), warp tile 64x64, 4-stage cp.async.
// R10 config + full-tile fragment hoist: all 16 LDSMs issued before the 64 MMAs,
// so chunk-1 LDS latency hides under chunk-0 MMA work.
#define KW    20
#define NSTG  4
#define AW    (128 * KW)                       // A words per stage
#define STGW  ((128 + 256) * KW)               // 7680 words per stage
#define GEMM_SMEM (NSTG * STGW * 4)            // 122880 B

__global__ __launch_bounds__(256, 1) void gemm_fp16ca(const __half* __restrict__ A,
                                                      const __half* __restrict__ B,
                                                      float* __restrict__ C,
                                                      int M, int N, int K) {
    extern __shared__ uint32_t sm[];
    const int t = threadIdx.x;
    const int w = t >> 5, lane = t & 31;
    const int wm = w >> 2, wn = w & 3;         // 2x4 warp grid, warp tile 64x64
    const int g = lane >> 2, cc = lane & 3;
    const int m0 = blockIdx.y * 128, n0 = blockIdx.x * 256;
    const int KT = K >> 5;
    const uint32_t sbase = smem_u32(sm);

    // cp.async: A 512 chunks (2/thread, same row), B 1024 chunks (4/thread, rows +64j)
    const int ar = t >> 1, ac = (t & 1) * 2;
    const __half* AgA = A + (size_t)(m0 + ar) * K + ac * 8;
    const uint32_t saA = sbase + (ar * KW + ac * 4) * 4;
    const int br = t >> 2, bc = t & 3;
    const __half* BgB = B + (size_t)(n0 + br) * K + bc * 8;
    const uint32_t saB = sbase + AW * 4 + (br * KW + bc * 4) * 4;

    // ldmatrix per-lane word offsets (within stage)
    const int lrow = lane & 7, sel = lane >> 3;
    uint32_t a_woff[4], b_woff[4];
#pragma unroll
    for (int mt = 0; mt < 4; mt++)
        a_woff[mt] = (uint32_t)((wm * 64 + mt * 16 + lrow + (sel & 1) * 8) * KW +
                                (sel >> 1) * 4);
#pragma unroll
    for (int p = 0; p < 4; p++)
        b_woff[p] = (uint32_t)(AW + (wn * 64 + p * 16 + (sel >> 1) * 8 + lrow) * KW +
                               (sel & 1) * 4);

    // prologue: stages 0..NSTG-2
#pragma unroll
    for (int s = 0; s < NSTG - 1; s++) {
        const uint32_t so = s * STGW * 4;
        const size_t ko = (size_t)s * 32;
        cp16(saA + so, AgA + ko);
        cp16(saA + so + 16, AgA + ko + 8);
#pragma unroll
        for (int j = 0; j < 4; j++)
            cp16(saB + so + j * (64 * KW * 4), BgB + (size_t)(64 * j) * K + ko);
        CP_COMMIT();
    }

    float acc[4][8][4];
#pragma unroll
    for (int mt = 0; mt < 4; mt++)
#pragma unroll
        for (int nt = 0; nt < 8; nt++)
#pragma unroll
            for (int q = 0; q < 4; q++) acc[mt][nt][q] = 0.f;

    for (int kt = 0; kt < KT; kt++) {
        CP_WAIT(2);
        __syncthreads();
        if (kt + NSTG - 1 < KT) {
            const uint32_t so = ((kt + NSTG - 1) % NSTG) * STGW * 4;
            const size_t ko = (size_t)(kt + NSTG - 1) * 32;
            cp16(saA + so, AgA + ko);
            cp16(saA + so + 16, AgA + ko + 8);
#pragma unroll
            for (int j = 0; j < 4; j++)
                cp16(saB + so + j * (64 * KW * 4), BgB + (size_t)(64 * j) * K + ko);
        }
        CP_COMMIT();

        const uint32_t stgoff = sbase + ((kt % NSTG) * STGW) * 4;
        // hoist ALL fragment loads for both k16 chunks
        uint32_t af[2][4][4], bf[2][4][4];
#pragma unroll
        for (int hh = 0; hh < 2; hh++) {
            const uint32_t kwb = stgoff + hh * 8 * 4;
#pragma unroll
            for (int mt = 0; mt < 4; mt++)
                ldsm4(af[hh][mt][0], af[hh][mt][1], af[hh][mt][2], af[hh][mt][3],
                      kwb + a_woff[mt] * 4);
#pragma unroll
            for (int p = 0; p < 4; p++)
                ldsm4(bf[hh][p][0], bf[hh][p][1], bf[hh][p][2], bf[hh][p][3],
                      kwb + b_woff[p] * 4);
        }
#pragma unroll
        for (int hh = 0; hh < 2; hh++)
#pragma unroll
            for (int mt = 0; mt < 4; mt++)
#pragma unroll
                for (int nt = 0; nt < 8; nt++)
                    mma_fp16(acc[mt][nt][0], acc[mt][nt][1], acc[mt][nt][2], acc[mt][nt][3],
                             af[hh][mt][0], af[hh][mt][1], af[hh][mt][2], af[hh][mt][3],
                             bf[hh][nt >> 1][(nt & 1) * 2], bf[hh][nt >> 1][(nt & 1) * 2 + 1]);
    }

#pragma unroll
    for (int mt = 0; mt < 4; mt++) {
        const int r = m0 + wm * 64 + mt * 16 + g;
#pragma unroll
        for (int nt = 0; nt < 8; nt++) {
            const int n = n0 + wn * 64 + nt * 8 + 2 * cc;
            *(float2*)&C[(size_t)r * N + n]       = make_float2(acc[mt][nt][0], acc[mt][nt][1]);
            *(float2*)&C[(size_t)(r + 8) * N + n] = make_float2(acc[mt][nt][2], acc[mt][nt][3]);
        }
    }
}

// ---------------- RoPE ----------------
__global__ __launch_bounds__(256) void rope2_kernel(float* __restrict__ proj,
                                                    const int* __restrict__ pos_ids) {
    __shared__ float ca[64], sa[64];
    const int s = blockIdx.x;
    const int t = threadIdx.x;
    if (t < 64) {
        const int pos = pos_ids[s];
        double inv = exp(-((double)t / 64.0) * 9.210340371976184);
        double a = (double)pos * inv;
        const double twopi = 6.283185307179586476925286766559;
        a -= floor(a / twopi) * twopi;
        sa[t] = sinf((float)a);
        ca[t] = cosf((float)a);
    }
    __syncthreads();
    float* base = proj + (size_t)s * P3;
#pragma unroll
    for (int it = 0; it < 16; it++) {
        const int p = t + it * 256;
        const int d = p & 63;
        const int hh = (p >> 6) & 31;
        float* ptr = base + ((p >> 11) ? HID : 0) + hh * HD + d;
        const float x1 = ptr[0], x2 = ptr[64];
        const float c = ca[d], sn = sa[d];
        ptr[0]  = x1 * c - x2 * sn;
        ptr[64] = x2 * c + x1 * sn;
    }
}

// ---------------- bf16-split tensor-core flash attention (unchanged) ----------------
#define QSTR 136
#define VSTR 72
#define SSTR 65
#define OFF_QH  0
#define OFF_QL  (OFF_QH + 128 * QSTR * 2)
#define OFF_KH  (OFF_QL + 128 * QSTR * 2)
#define OFF_KL  (OFF_KH + 64 * QSTR * 2)
#define OFF_VTH (OFF_KL + 64 * QSTR * 2)
#define OFF_VTL (OFF_VTH + 128 * VSTR * 2)
#define OFF_SF  (OFF_VTL + 128 * VSTR * 2)
#define OFF_PH  (OFF_SF + 128 * SSTR * 4)
#define OFF_PL  (OFF_PH + 128 * VSTR * 2)
#define OFF_ST  (OFF_PL + 128 * VSTR * 2)
#define ATTN2_SMEM (OFF_ST + 3 * 128 * 4)

__global__ __launch_bounds__(256, 1) void attn_bf16(const float* __restrict__ proj,
                                                    float* __restrict__ attn_out) {
    extern __shared__ char smraw[];
    uint32_t* Qh  = (uint32_t*)(smraw + OFF_QH);
    uint32_t* Ql  = (uint32_t*)(smraw + OFF_QL);
    uint32_t* Kh  = (uint32_t*)(smraw + OFF_KH);
    uint32_t* Kl  = (uint32_t*)(smraw + OFF_KL);
    uint32_t* Vth = (uint32_t*)(smraw + OFF_VTH);
    uint32_t* Vtl = (uint32_t*)(smraw + OFF_VTL);
    float*    Sf  = (float*)(smraw + OFF_SF);
    uint32_t* Ph  = (uint32_t*)(smraw + OFF_PH);
    uint32_t* Pl  = (uint32_t*)(smraw + OFF_PL);
    float*    rowM = (float*)(smraw + OFF_ST);
    float*    rowL = rowM + 128;
    float*    rowA = rowL + 128;

    const int t = threadIdx.x;
    const int w = t >> 5, lane = t & 31;
    const int g = lane >> 2, cc = lane & 3;
    const int h = blockIdx.x;
    const int qt = 15 - (int)blockIdx.y;
    const int qbase = qt * 128;
    const int qcol = h * HD, kcol = HID + h * HD, vcol = 2 * HID + h * HD;

    {
        const int row = t >> 1;
        const int c0 = (t & 1) * 64;
        const float* src = proj + (size_t)(qbase + row) * P3 + qcol + c0;
        uint32_t* qh = Qh + row * 68 + (c0 >> 1);
        uint32_t* ql = Ql + row * 68 + (c0 >> 1);
#pragma unroll
        for (int i = 0; i < 16; i++) {
            float4 v = *(const float4*)(src + i * 4);
            uint32_t hp, lp;
            split_pair(v.x * NORM, v.y * NORM, hp, lp);
            qh[2 * i] = hp; ql[2 * i] = lp;
            split_pair(v.z * NORM, v.w * NORM, hp, lp);
            qh[2 * i + 1] = hp; ql[2 * i + 1] = lp;
        }
    }
    if (t < 128) { rowM[t] = -3.0e38f; rowL[t] = 0.f; }

    float oacc[16][4];
#pragma unroll
    for (int nt = 0; nt < 16; nt++)
#pragma unroll
        for (int q = 0; q < 4; q++) oacc[nt][q] = 0.f;

    const int nkt = 2 * qt + 2;
    for (int j = 0; j < nkt; j++) {
        __syncthreads();
        {
            const int r = t >> 2;
            const int c0 = (t & 3) * 32;
            const float* src = proj + (size_t)(j * 64 + r) * P3 + kcol + c0;
            uint32_t* kh = Kh + r * 68 + (c0 >> 1);
            uint32_t* kl = Kl + r * 68 + (c0 >> 1);
#pragma unroll
            for (int i = 0; i < 8; i++) {
                float4 v = *(const float4*)(src + i * 4);
                uint32_t hp, lp;
                split_pair(v.x, v.y, hp, lp);
                kh[2 * i] = hp; kl[2 * i] = lp;
                split_pair(v.z, v.w, hp, lp);
                kh[2 * i + 1] = hp; kl[2 * i + 1] = lp;
            }
        }
        {
            const int c = (t & 31) + ((t >> 5) & 3) * 32;
            const int rp0 = (t >> 7) * 16;
            const float* vsrc = proj + (size_t)(j * 64) * P3 + vcol + c;
#pragma unroll
            for (int it = 0; it < 16; it++) {
                const int rp = rp0 + it;
                const float v0 = vsrc[(size_t)(2 * rp) * P3];
                const float v1 = vsrc[(size_t)(2 * rp + 1) * P3];
                uint32_t hp, lp;
                split_pair(v0, v1, hp, lp);
                Vth[c * 36 + rp] = hp;
                Vtl[c * 36 + rp] = lp;
            }
        }
        __syncthreads();

        float sacc[8][4];
#pragma unroll
        for (int nt = 0; nt < 8; nt++)
#pragma unroll
            for (int q = 0; q < 4; q++) sacc[nt][q] = 0.f;

        const uint32_t* q0 = Qh + (w * 16 + g) * 68;
        const uint32_t* q1 = q0 + 8 * 68;
        const uint32_t* q0l = Ql + (w * 16 + g) * 68;
        const uint32_t* q1l = q0l + 8 * 68;
#pragma unroll
        for (int kc = 0; kc < 8; kc++) {
            const int kw = kc * 8;
            uint32_t ah0 = q0[kw + cc], ah1 = q1[kw + cc];
            uint32_t ah2 = q0[kw + cc + 4], ah3 = q1[kw + cc + 4];
            uint32_t al0 = q0l[kw + cc], al1 = q1l[kw + cc];
            uint32_t al2 = q0l[kw + cc + 4], al3 = q1l[kw + cc + 4];
#pragma unroll
            for (int nt = 0; nt < 8; nt++) {
                const int nw = (nt * 8 + g) * 68 + kw;
                uint32_t bh0 = Kh[nw + cc], bh1 = Kh[nw + cc + 4];
                uint32_t bl0 = Kl[nw + cc], bl1 = Kl[nw + cc + 4];
                mma_bf16(sacc[nt][0], sacc[nt][1], sacc[nt][2], sacc[nt][3],
                         ah0, ah1, ah2, ah3, bh0, bh1);
                mma_bf16(sacc[nt][0], sacc[nt][1], sacc[nt][2], sacc[nt][3],
                         ah0, ah1, ah2, ah3, bl0, bl1);
                mma_bf16(sacc[nt][0], sacc[nt][1], sacc[nt][2], sacc[nt][3],
                         al0, al1, al2, al3, bh0, bh1);
            }
        }
        {
            const bool diagt = (j * 64 + 63 > qbase);
            const int r0g = qbase + w * 16 + g;
            float* s0 = Sf + (w * 16 + g) * SSTR;
            float* s1 = s0 + 8 * SSTR;
#pragma unroll
            for (int nt = 0; nt < 8; nt++) {
                const int cg = j * 64 + nt * 8 + 2 * cc;
                float v0 = sacc[nt][0], v1 = sacc[nt][1];
                float v2 = sacc[nt][2], v3 = sacc[nt][3];
                if (diagt) {
                    if (cg     > r0g)     v0 = -1.0e9f;
                    if (cg + 1 > r0g)     v1 = -1.0e9f;
                    if (cg     > r0g + 8) v2 = -1.0e9f;
                    if (cg + 1 > r0g + 8) v3 = -1.0e9f;
                }
                s0[nt * 8 + 2 * cc] = v0; s0[nt * 8 + 2 * cc + 1] = v1;
                s1[nt * 8 + 2 * cc] = v2; s1[nt * 8 + 2 * cc + 1] = v3;
            }
        }
        __syncthreads();

        {
            const int row = t >> 1, half = t & 1;
            const float* pr = Sf + row * SSTR + half * 32;
            float m = -3.0e38f;
#pragma unroll 8
            for (int i = 0; i < 32; i++) m = fmaxf(m, pr[i]);
            m = fmaxf(m, __shfl_xor_sync(0xFFFFFFFFu, m, 1));
            const float mold = rowM[row];
            const float mnew = fmaxf(mold, m);
            float ssum = 0.f;
            uint32_t* ph = Ph + row * 36 + half * 16;
            uint32_t* pl = Pl + row * 36 + half * 16;
#pragma unroll 4
            for (int i = 0; i < 16; i++) {
                const float p0 = __expf(pr[2 * i] - mnew);
                const float p1 = __expf(pr[2 * i + 1] - mnew);
                ssum += p0 + p1;
                uint32_t hp, lp;
                split_pair(p0, p1, hp, lp);
                ph[i] = hp; pl[i] = lp;
            }
            ssum += __shfl_xor_sync(0xFFFFFFFFu, ssum, 1);
            if (half == 0) {
                const float alpha = __expf(mold - mnew);
                rowA[row] = alpha;
                rowL[row] = rowL[row] * alpha + ssum;
                rowM[row] = mnew;
            }
        }
        __syncthreads();

        {
            const float al0 = rowA[w * 16 + g], al1 = rowA[w * 16 + 8 + g];
#pragma unroll
            for (int nt = 0; nt < 16; nt++) {
                oacc[nt][0] *= al0; oacc[nt][1] *= al0;
                oacc[nt][2] *= al1; oacc[nt][3] *= al1;
            }
            const uint32_t* p0 = Ph + (w * 16 + g) * 36;
            const uint32_t* p1 = p0 + 8 * 36;
            const uint32_t* p0l = Pl + (w * 16 + g) * 36;
            const uint32_t* p1l = p0l + 8 * 36;
#pragma unroll
            for (int kc = 0; kc < 4; kc++) {
                const int kw = kc * 8;
                uint32_t ah0 = p0[kw + cc], ah1 = p1[kw + cc];
                uint32_t ah2 = p0[kw + cc + 4], ah3 = p1[kw + cc + 4];
                uint32_t al0f = p0l[kw + cc], al1f = p1l[kw + cc];
                uint32_t al2f = p0l[kw + cc + 4], al3f = p1l[kw + cc + 4];
#pragma unroll
                for (int nt = 0; nt < 16; nt++) {
                    const int nw = (nt * 8 + g) * 36 + kw;
                    uint32_t bh0 = Vth[nw + cc], bh1 = Vth[nw + cc + 4];
                    uint32_t bl0 = Vtl[nw + cc], bl1 = Vtl[nw + cc + 4];
                    mma_bf16(oacc[nt][0], oacc[nt][1], oacc[nt][2], oacc[nt][3],
                             ah0, ah1, ah2, ah3, bh0, bh1);
                    mma_bf16(oacc[nt][0], oacc[nt][1], oacc[nt][2], oacc[nt][3],
                             ah0, ah1, ah2, ah3, bl0, bl1);
                    mma_bf16(oacc[nt][0], oacc[nt][1], oacc[nt][2], oacc[nt][3],
                             al0f, al1f, al2f, al3f, bh0, bh1);
                }
            }
        }
    }

    {
        const float il0 = 1.0f / rowL[w * 16 + g];
        const float il1 = 1.0f / rowL[w * 16 + 8 + g];
        const size_t base0 = (size_t)(qbase + w * 16 + g) * HID + h * HD + 2 * cc;
#pragma unroll
        for (int nt = 0; nt < 16; nt++) {
            *(float2*)(attn_out + base0 + nt * 8) =
                make_float2(oacc[nt][0] * il0, oacc[nt][1] * il0);
            *(float2*)(attn_out + base0 + 8 * HID + nt * 8) =
                make_float2(oacc[nt][2] * il1, oacc[nt][3] * il1);
        }
    }
}

// ---------------- launch ----------------
extern "C" void kernel_launch(void* const* d_in, const int* in_sizes, int n_in,
                              void* d_out, int out_size) {
    (void)in_sizes; (void)n_in; (void)out_size;
    const float* hidden  = (const float*)d_in[0];
    const int*   pos_ids = (const int*)d_in[2];
    const float* W_pack  = (const float*)d_in[3];
    const float* W_o     = (const float*)d_in[4];
    float* out = (float*)d_out;

    float *proj = nullptr, *attn = nullptr;
    __half *hid_h = nullptr, *wp_h = nullptr, *wo_h = nullptr, *attn_h = nullptr;
    cudaGetSymbolAddress((void**)&proj, g_proj);
    cudaGetSymbolAddress((void**)&attn, g_attn);
    cudaGetSymbolAddress((void**)&hid_h, g_hid_h);
    cudaGetSymbolAddress((void**)&wp_h, g_wp_h);
    cudaGetSymbolAddress((void**)&wo_h, g_wo_h);
    cudaGetSymbolAddress((void**)&attn_h, g_attn_h);
    cudaFuncSetAttribute(attn_bf16, cudaFuncAttributeMaxDynamicSharedMemorySize, ATTN2_SMEM);
    cudaFuncSetAttribute(gemm_fp16ca, cudaFuncAttributeMaxDynamicSharedMemorySize, GEMM_SMEM);

    // converts (bandwidth-bound)
    f2h_kernel<<<(S_LEN * HID) / (256 * 8), 256>>>(hidden, hid_h, S_LEN * HID);
    f2h_kernel<<<(P3 * HID) / (256 * 8), 256>>>(W_pack, wp_h, P3 * HID);
    f2h_kernel<<<(HID * HID) / (256 * 8), 256>>>(W_o, wo_h, HID * HID);

    // 1) QKV projection (fp16 cp.async + ldmatrix, hoisted fragments)
    gemm_fp16ca<<<dim3(P3 / 256, S_LEN / 128), 256, GEMM_SMEM>>>(hid_h, wp_h, proj,
                                                                 S_LEN, P3, HID);
    // 2) RoPE in-place on Q,K
    rope2_kernel<<<S_LEN, 256>>>(proj, pos_ids);
    // 3) causal flash attention (bf16-split tensor cores)
    attn_bf16<<<dim3(NH, S_LEN / 128), 256, ATTN2_SMEM>>>(proj, attn);
    // 4) output projection
    f2h_kernel<<<(S_LEN * HID) / (256 * 8), 256>>>(attn, attn_h, S_LEN * HID);
    gemm_fp16ca<<<dim3(HID / 256, S_LEN / 128), 256, GEMM_SMEM>>>(attn_h, wo_h, out,
                                                                  S_LEN, HID, HID);
}

// round 15
// speedup vs baseline: 1.2962x; 1.1079x over previous
#include <cuda_runtime.h>
#include <cuda_fp16.h>
#include <cstdint>
#include <cstddef>

#define S_LEN 2048
#define HID   4096
#define NH    32
#define HD    128
#define P3    12288   // 3*HID
#define NORM  0.08838834764831845f   // 1/sqrt(128)

// ---------------- scratch (no allocations allowed) ----------------
__device__ float  g_proj[S_LEN * P3];
__device__ __half g_hid_h[S_LEN * HID];
__device__ __half g_wp_h[P3 * HID];
__device__ __half g_wo_h[HID * HID];
__device__ __half g_attn_h[S_LEN * HID];

// ---------------- helpers ----------------
__device__ __forceinline__ uint32_t smem_u32(const void* p) {
    uint32_t a;
    asm("{ .reg .u64 t; cvta.to.shared.u64 t, %1; cvt.u32.u64 %0, t; }" : "=r"(a) : "l"(p));
    return a;
}
__device__ __forceinline__ void cp16(uint32_t saddr, const void* gptr) {
    asm volatile("cp.async.ca.shared.global [%0], [%1], 16;" :: "r"(saddr), "l"(gptr));
}
#define CP_COMMIT() asm volatile("cp.async.commit_group;" ::: "memory")
#define CP_WAIT(n)  asm volatile("cp.async.wait_group %0;" :: "n"(n) : "memory")

__device__ __forceinline__ void ldsm4(uint32_t& r0, uint32_t& r1, uint32_t& r2, uint32_t& r3,
                                      uint32_t addr) {
    asm volatile("ldmatrix.sync.aligned.m8n8.x4.shared.b16 {%0,%1,%2,%3}, [%4];"
                 : "=r"(r0), "=r"(r1), "=r"(r2), "=r"(r3) : "r"(addr));
}

// mma.sync m16n8k16 fp16, fp32 accum
__device__ __forceinline__ void mma_fp16(float& c0, float& c1, float& c2, float& c3,
                                         uint32_t a0, uint32_t a1, uint32_t a2, uint32_t a3,
                                         uint32_t b0, uint32_t b1) {
    asm volatile(
        "mma.sync.aligned.m16n8k16.row.col.f32.f16.f16.f32 "
        "{%0,%1,%2,%3}, {%4,%5,%6,%7}, {%8,%9}, {%0,%1,%2,%3};"
        : "+f"(c0), "+f"(c1), "+f"(c2), "+f"(c3)
        : "r"(a0), "r"(a1), "r"(a2), "r"(a3), "r"(b0), "r"(b1));
}
// mma.sync m16n8k16 bf16 (attention)
__device__ __forceinline__ void mma_bf16(float& c0, float& c1, float& c2, float& c3,
                                         uint32_t a0, uint32_t a1, uint32_t a2, uint32_t a3,
                                         uint32_t b0, uint32_t b1) {
    asm volatile(
        "mma.sync.aligned.m16n8k16.row.col.f32.bf16.bf16.f32 "
        "{%0,%1,%2,%3}, {%4,%5,%6,%7}, {%8,%9}, {%0,%1,%2,%3};"
        : "+f"(c0), "+f"(c1), "+f"(c2), "+f"(c3)
        : "r"(a0), "r"(a1), "r"(a2), "r"(a3), "r"(b0), "r"(b1));
}
__device__ __forceinline__ void split_pair(float x0, float x1, uint32_t& hp, uint32_t& lp) {
    uint16_t h0, h1, l0, l1;
    asm("cvt.rn.bf16.f32 %0, %1;" : "=h"(h0) : "f"(x0));
    asm("cvt.rn.bf16.f32 %0, %1;" : "=h"(h1) : "f"(x1));
    float r0 = x0 - __uint_as_float((uint32_t)h0 << 16);
    float r1 = x1 - __uint_as_float((uint32_t)h1 << 16);
    asm("cvt.rn.bf16.f32 %0, %1;" : "=h"(l0) : "f"(r0));
    asm("cvt.rn.bf16.f32 %0, %1;" : "=h"(l1) : "f"(r1));
    asm("mov.b32 %0, {%1, %2};" : "=r"(hp) : "h"(h0), "h"(h1));
    asm("mov.b32 %0, {%1, %2};" : "=r"(lp) : "h"(l0), "h"(l1));
}

// ---------------- fp32 -> fp16 convert ----------------
__global__ __launch_bounds__(256) void f2h_kernel(const float* __restrict__ src,
                                                  __half* __restrict__ dst, int n) {
    int i = (blockIdx.x * blockDim.x + threadIdx.x) * 8;
    if (i >= n) return;
    float4 a = *(const float4*)(src + i);
    float4 b = *(const float4*)(src + i + 4);
    __half2 h0 = __floats2half2_rn(a.x, a.y);
    __half2 h1 = __floats2half2_rn(a.z, a.w);
    __half2 h2 = __floats2half2_rn(b.x, b.y);
    __half2 h3 = __floats2half2_rn(b.z, b.w);
    uint4 v = {*(uint32_t*)&h0, *(uint32_t*)&h1, *(uint32_t*)&h2, *(uint32_t*)&h3};
    *(uint4*)(dst + i) = v;
}

// ---------------- fp16 cp.async + ldmatrix GEMM: C = A * B^T (R10 config) ----------------
#define KW    20
#define NSTG  4
#define AW    (128 * KW)
#define STGW  ((128 + 256) * KW)
#define GEMM_SMEM (NSTG * STGW * 4)            // 122880 B

__global__ __launch_bounds__(256, 1) void gemm_fp16ca(const __half* __restrict__ A,
                                                      const __half* __restrict__ B,
                                                      float* __restrict__ C,
                                                      int M, int N, int K) {
    extern __shared__ uint32_t sm[];
    const int t = threadIdx.x;
    const int w = t >> 5, lane = t & 31;
    const int wm = w >> 2, wn = w & 3;
    const int g = lane >> 2, cc = lane & 3;
    const int m0 = blockIdx.y * 128, n0 = blockIdx.x * 256;
    const int KT = K >> 5;
    const uint32_t sbase = smem_u32(sm);

    const int ar = t >> 1, ac = (t & 1) * 2;
    const __half* AgA = A + (size_t)(m0 + ar) * K + ac * 8;
    const uint32_t saA = sbase + (ar * KW + ac * 4) * 4;
    const int br = t >> 2, bc = t & 3;
    const __half* BgB = B + (size_t)(n0 + br) * K + bc * 8;
    const uint32_t saB = sbase + AW * 4 + (br * KW + bc * 4) * 4;

    const int lrow = lane & 7, sel = lane >> 3;
    uint32_t a_woff[4], b_woff[4];
#pragma unroll
    for (int mt = 0; mt < 4; mt++)
        a_woff[mt] = (uint32_t)((wm * 64 + mt * 16 + lrow + (sel & 1) * 8) * KW +
                                (sel >> 1) * 4);
#pragma unroll
    for (int p = 0; p < 4; p++)
        b_woff[p] = (uint32_t)(AW + (wn * 64 + p * 16 + (sel >> 1) * 8 + lrow) * KW +
                               (sel & 1) * 4);

#pragma unroll
    for (int s = 0; s < NSTG - 1; s++) {
        const uint32_t so = s * STGW * 4;
        const size_t ko = (size_t)s * 32;
        cp16(saA + so, AgA + ko);
        cp16(saA + so + 16, AgA + ko + 8);
#pragma unroll
        for (int j = 0; j < 4; j++)
            cp16(saB + so + j * (64 * KW * 4), BgB + (size_t)(64 * j) * K + ko);
        CP_COMMIT();
    }

    float acc[4][8][4];
#pragma unroll
    for (int mt = 0; mt < 4; mt++)
#pragma unroll
        for (int nt = 0; nt < 8; nt++)
#pragma unroll
            for (int q = 0; q < 4; q++) acc[mt][nt][q] = 0.f;

    for (int kt = 0; kt < KT; kt++) {
        CP_WAIT(2);
        __syncthreads();
        if (kt + NSTG - 1 < KT) {
            const uint32_t so = ((kt + NSTG - 1) % NSTG) * STGW * 4;
            const size_t ko = (size_t)(kt + NSTG - 1) * 32;
            cp16(saA + so, AgA + ko);
            cp16(saA + so + 16, AgA + ko + 8);
#pragma unroll
            for (int j = 0; j < 4; j++)
                cp16(saB + so + j * (64 * KW * 4), BgB + (size_t)(64 * j) * K + ko);
        }
        CP_COMMIT();

        const uint32_t stgoff = sbase + ((kt % NSTG) * STGW) * 4;
#pragma unroll
        for (int hh = 0; hh < 2; hh++) {
            const uint32_t kwb = stgoff + hh * 8 * 4;
            uint32_t af[4][4], bf[4][4];
#pragma unroll
            for (int mt = 0; mt < 4; mt++)
                ldsm4(af[mt][0], af[mt][1], af[mt][2], af[mt][3], kwb + a_woff[mt] * 4);
#pragma unroll
            for (int p = 0; p < 4; p++)
                ldsm4(bf[p][0], bf[p][1], bf[p][2], bf[p][3], kwb + b_woff[p] * 4);
#pragma unroll
            for (int mt = 0; mt < 4; mt++)
#pragma unroll
                for (int nt = 0; nt < 8; nt++)
                    mma_fp16(acc[mt][nt][0], acc[mt][nt][1], acc[mt][nt][2], acc[mt][nt][3],
                             af[mt][0], af[mt][1], af[mt][2], af[mt][3],
                             bf[nt >> 1][(nt & 1) * 2], bf[nt >> 1][(nt & 1) * 2 + 1]);
        }
    }

#pragma unroll
    for (int mt = 0; mt < 4; mt++) {
        const int r = m0 + wm * 64 + mt * 16 + g;
#pragma unroll
        for (int nt = 0; nt < 8; nt++) {
            const int n = n0 + wn * 64 + nt * 8 + 2 * cc;
            *(float2*)&C[(size_t)r * N + n]       = make_float2(acc[mt][nt][0], acc[mt][nt][1]);
            *(float2*)&C[(size_t)(r + 8) * N + n] = make_float2(acc[mt][nt][2], acc[mt][nt][3]);
        }
    }
}

// ---------------- RoPE ----------------
__global__ __launch_bounds__(256) void rope2_kernel(float* __restrict__ proj,
                                                    const int* __restrict__ pos_ids) {
    __shared__ float ca[64], sa[64];
    const int s = blockIdx.x;
    const int t = threadIdx.x;
    if (t < 64) {
        const int pos = pos_ids[s];
        double inv = exp(-((double)t / 64.0) * 9.210340371976184);
        double a = (double)pos * inv;
        const double twopi = 6.283185307179586476925286766559;
        a -= floor(a / twopi) * twopi;
        sa[t] = sinf((float)a);
        ca[t] = cosf((float)a);
    }
    __syncthreads();
    float* base = proj + (size_t)s * P3;
#pragma unroll
    for (int it = 0; it < 16; it++) {
        const int p = t + it * 256;
        const int d = p & 63;
        const int hh = (p >> 6) & 31;
        float* ptr = base + ((p >> 11) ? HID : 0) + hh * HD + d;
        const float x1 = ptr[0], x2 = ptr[64];
        const float c = ca[d], sn = sa[d];
        ptr[0]  = x1 * c - x2 * sn;
        ptr[64] = x2 * c + x1 * sn;
    }
}

// ---------------- register-resident bf16-split flash attention ----------------
// Score fragments stay in registers: in-warp softmax via shfl (warp owns full rows),
// P split to bf16 in-register (frag layout of QK output == PV A input). 2 barriers/ktile.
#define OFF_QH  0
#define OFF_QL  (OFF_QH + 128 * 136 * 2)      // 34816
#define OFF_KH  (OFF_QL + 128 * 136 * 2)      // 69632
#define OFF_KL  (OFF_KH + 64 * 136 * 2)       // 87040
#define OFF_VTH (OFF_KL + 64 * 136 * 2)       // 104448
#define OFF_VTL (OFF_VTH + 128 * 72 * 2)      // 122880
#define ATTN3_SMEM (OFF_VTL + 128 * 72 * 2)   // 141312

__global__ __launch_bounds__(256, 1) void attn_reg(const float* __restrict__ proj,
                                                   __half* __restrict__ attn_out_h) {
    extern __shared__ char smraw[];
    uint32_t* Qh  = (uint32_t*)(smraw + OFF_QH);    // word stride 68
    uint32_t* Ql  = (uint32_t*)(smraw + OFF_QL);
    uint32_t* Kh  = (uint32_t*)(smraw + OFF_KH);
    uint32_t* Kl  = (uint32_t*)(smraw + OFF_KL);
    uint32_t* Vth = (uint32_t*)(smraw + OFF_VTH);   // word stride 36, [dim][kv-pair]
    uint32_t* Vtl = (uint32_t*)(smraw + OFF_VTL);

    const int t = threadIdx.x;
    const int w = t >> 5, lane = t & 31;
    const int g = lane >> 2, cc = lane & 3;
    const int h = blockIdx.x;
    const int qt = 15 - (int)blockIdx.y;
    const int qbase = qt * 128;
    const int qcol = h * HD, kcol = HID + h * HD, vcol = 2 * HID + h * HD;

    // ---- load + split Q (scaled by NORM) ----
    {
        const int row = t >> 1;
        const int c0 = (t & 1) * 64;
        const float* src = proj + (size_t)(qbase + row) * P3 + qcol + c0;
        uint32_t* qh = Qh + row * 68 + (c0 >> 1);
        uint32_t* ql = Ql + row * 68 + (c0 >> 1);
#pragma unroll
        for (int i = 0; i < 16; i++) {
            float4 v = *(const float4*)(src + i * 4);
            uint32_t hp, lp;
            split_pair(v.x * NORM, v.y * NORM, hp, lp);
            qh[2 * i] = hp; ql[2 * i] = lp;
            split_pair(v.z * NORM, v.w * NORM, hp, lp);
            qh[2 * i + 1] = hp; ql[2 * i + 1] = lp;
        }
    }

    float rowM0 = -3.0e38f, rowM1 = -3.0e38f, rowL0 = 0.f, rowL1 = 0.f;
    float oacc[16][4];
#pragma unroll
    for (int nt = 0; nt < 16; nt++)
#pragma unroll
        for (int q = 0; q < 4; q++) oacc[nt][q] = 0.f;

    const int nkt = 2 * qt + 2;
    for (int j = 0; j < nkt; j++) {
        __syncthreads();   // prev QK/PV reads of K/V done (and Q split visible, j=0)
        // ---- load + split K ----
        {
            const int r = t >> 2;
            const int c0 = (t & 3) * 32;
            const float* src = proj + (size_t)(j * 64 + r) * P3 + kcol + c0;
            uint32_t* kh = Kh + r * 68 + (c0 >> 1);
            uint32_t* kl = Kl + r * 68 + (c0 >> 1);
#pragma unroll
            for (int i = 0; i < 8; i++) {
                float4 v = *(const float4*)(src + i * 4);
                uint32_t hp, lp;
                split_pair(v.x, v.y, hp, lp);
                kh[2 * i] = hp; kl[2 * i] = lp;
                split_pair(v.z, v.w, hp, lp);
                kh[2 * i + 1] = hp; kl[2 * i + 1] = lp;
            }
        }
        // ---- load + split + transpose V ----
        {
            const int c = (t & 31) + ((t >> 5) & 3) * 32;
            const int rp0 = (t >> 7) * 16;
            const float* vsrc = proj + (size_t)(j * 64) * P3 + vcol + c;
#pragma unroll
            for (int it = 0; it < 16; it++) {
                const int rp = rp0 + it;
                const float v0 = vsrc[(size_t)(2 * rp) * P3];
                const float v1 = vsrc[(size_t)(2 * rp + 1) * P3];
                uint32_t hp, lp;
                split_pair(v0, v1, hp, lp);
                Vth[c * 36 + rp] = hp;
                Vtl[c * 36 + rp] = lp;
            }
        }
        __syncthreads();

        // ---- scores (3-MMA bf16 split) ----
        float sacc[8][4];
#pragma unroll
        for (int nt = 0; nt < 8; nt++)
#pragma unroll
            for (int q = 0; q < 4; q++) sacc[nt][q] = 0.f;

        const uint32_t* q0 = Qh + (w * 16 + g) * 68;
        const uint32_t* q1 = q0 + 8 * 68;
        const uint32_t* q0l = Ql + (w * 16 + g) * 68;
        const uint32_t* q1l = q0l + 8 * 68;
#pragma unroll
        for (int kc = 0; kc < 8; kc++) {
            const int kw = kc * 8;
            uint32_t ah0 = q0[kw + cc], ah1 = q1[kw + cc];
            uint32_t ah2 = q0[kw + cc + 4], ah3 = q1[kw + cc + 4];
            uint32_t al0 = q0l[kw + cc], al1 = q1l[kw + cc];
            uint32_t al2 = q0l[kw + cc + 4], al3 = q1l[kw + cc + 4];
#pragma unroll
            for (int nt = 0; nt < 8; nt++) {
                const int nw = (nt * 8 + g) * 68 + kw;
                uint32_t bh0 = Kh[nw + cc], bh1 = Kh[nw + cc + 4];
                uint32_t bl0 = Kl[nw + cc], bl1 = Kl[nw + cc + 4];
                mma_bf16(sacc[nt][0], sacc[nt][1], sacc[nt][2], sacc[nt][3],
                         ah0, ah1, ah2, ah3, bh0, bh1);
                mma_bf16(sacc[nt][0], sacc[nt][1], sacc[nt][2], sacc[nt][3],
                         ah0, ah1, ah2, ah3, bl0, bl1);
                mma_bf16(sacc[nt][0], sacc[nt][1], sacc[nt][2], sacc[nt][3],
                         al0, al1, al2, al3, bh0, bh1);
            }
        }
        // ---- causal mask (registers) ----
        {
            const bool diagt = (j * 64 + 63 > qbase);
            if (diagt) {
                const int r0g = qbase + w * 16 + g;
#pragma unroll
                for (int nt = 0; nt < 8; nt++) {
                    const int cg = j * 64 + nt * 8 + 2 * cc;
                    if (cg     > r0g)     sacc[nt][0] = -1.0e9f;
                    if (cg + 1 > r0g)     sacc[nt][1] = -1.0e9f;
                    if (cg     > r0g + 8) sacc[nt][2] = -1.0e9f;
                    if (cg + 1 > r0g + 8) sacc[nt][3] = -1.0e9f;
                }
            }
        }
        // ---- in-register online softmax (rows owned by 4 cc-lanes) ----
        {
            float m0 = -3.0e38f, m1 = -3.0e38f;
#pragma unroll
            for (int nt = 0; nt < 8; nt++) {
                m0 = fmaxf(m0, fmaxf(sacc[nt][0], sacc[nt][1]));
                m1 = fmaxf(m1, fmaxf(sacc[nt][2], sacc[nt][3]));
            }
            m0 = fmaxf(m0, __shfl_xor_sync(0xFFFFFFFFu, m0, 1));
            m0 = fmaxf(m0, __shfl_xor_sync(0xFFFFFFFFu, m0, 2));
            m1 = fmaxf(m1, __shfl_xor_sync(0xFFFFFFFFu, m1, 1));
            m1 = fmaxf(m1, __shfl_xor_sync(0xFFFFFFFFu, m1, 2));
            const float mn0 = fmaxf(rowM0, m0), mn1 = fmaxf(rowM1, m1);
            const float al0 = __expf(rowM0 - mn0), al1 = __expf(rowM1 - mn1);
            rowM0 = mn0; rowM1 = mn1;
            float s0 = 0.f, s1 = 0.f;
#pragma unroll
            for (int nt = 0; nt < 8; nt++) {
                sacc[nt][0] = __expf(sacc[nt][0] - mn0);
                sacc[nt][1] = __expf(sacc[nt][1] - mn0);
                sacc[nt][2] = __expf(sacc[nt][2] - mn1);
                sacc[nt][3] = __expf(sacc[nt][3] - mn1);
                s0 += sacc[nt][0] + sacc[nt][1];
                s1 += sacc[nt][2] + sacc[nt][3];
            }
            s0 += __shfl_xor_sync(0xFFFFFFFFu, s0, 1);
            s0 += __shfl_xor_sync(0xFFFFFFFFu, s0, 2);
            s1 += __shfl_xor_sync(0xFFFFFFFFu, s1, 1);
            s1 += __shfl_xor_sync(0xFFFFFFFFu, s1, 2);
            rowL0 = rowL0 * al0 + s0;
            rowL1 = rowL1 * al1 + s1;
#pragma unroll
            for (int nt = 0; nt < 16; nt++) {
                oacc[nt][0] *= al0; oacc[nt][1] *= al0;
                oacc[nt][2] *= al1; oacc[nt][3] *= al1;
            }
        }
        // ---- PV: P fragments built in-register from sacc ----
#pragma unroll
        for (int kc = 0; kc < 4; kc++) {
            uint32_t ah0, ah1, ah2, ah3, pl0, pl1, pl2, pl3;
            split_pair(sacc[2 * kc][0],     sacc[2 * kc][1],     ah0, pl0);
            split_pair(sacc[2 * kc][2],     sacc[2 * kc][3],     ah1, pl1);
            split_pair(sacc[2 * kc + 1][0], sacc[2 * kc + 1][1], ah2, pl2);
            split_pair(sacc[2 * kc + 1][2], sacc[2 * kc + 1][3], ah3, pl3);
            const int kw = kc * 8;
#pragma unroll
            for (int nt = 0; nt < 16; nt++) {
                const int nw = (nt * 8 + g) * 36 + kw;
                uint32_t bh0 = Vth[nw + cc], bh1 = Vth[nw + cc + 4];
                uint32_t bl0 = Vtl[nw + cc], bl1 = Vtl[nw + cc + 4];
                mma_bf16(oacc[nt][0], oacc[nt][1], oacc[nt][2], oacc[nt][3],
                         ah0, ah1, ah2, ah3, bh0, bh1);
                mma_bf16(oacc[nt][0], oacc[nt][1], oacc[nt][2], oacc[nt][3],
                         ah0, ah1, ah2, ah3, bl0, bl1);
                mma_bf16(oacc[nt][0], oacc[nt][1], oacc[nt][2], oacc[nt][3],
                         pl0, pl1, pl2, pl3, bh0, bh1);
            }
        }
    }

    // ---- epilogue: O /= L, write fp16 directly ----
    {
        const float il0 = 1.0f / rowL0;
        const float il1 = 1.0f / rowL1;
        const size_t base0 = (size_t)(qbase + w * 16 + g) * HID + h * HD + 2 * cc;
#pragma unroll
        for (int nt = 0; nt < 16; nt++) {
            __half2 h0 = __floats2half2_rn(oacc[nt][0] * il0, oacc[nt][1] * il0);
            __half2 h1 = __floats2half2_rn(oacc[nt][2] * il1, oacc[nt][3] * il1);
            *(__half2*)(attn_out_h + base0 + nt * 8) = h0;
            *(__half2*)(attn_out_h + base0 + 8 * HID + nt * 8) = h1;
        }
    }
}

// ---------------- launch ----------------
extern "C" void kernel_launch(void* const* d_in, const int* in_sizes, int n_in,
                              void* d_out, int out_size) {
    (void)in_sizes; (void)n_in; (void)out_size;
    const float* hidden  = (const float*)d_in[0];
    const int*   pos_ids = (const int*)d_in[2];
    const float* W_pack  = (const float*)d_in[3];
    const float* W_o     = (const float*)d_in[4];
    float* out = (float*)d_out;

    float *proj = nullptr;
    __half *hid_h = nullptr, *wp_h = nullptr, *wo_h = nullptr, *attn_h = nullptr;
    cudaGetSymbolAddress((void**)&proj, g_proj);
    cudaGetSymbolAddress((void**)&hid_h, g_hid_h);
    cudaGetSymbolAddress((void**)&wp_h, g_wp_h);
    cudaGetSymbolAddress((void**)&wo_h, g_wo_h);
    cudaGetSymbolAddress((void**)&attn_h, g_attn_h);
    cudaFuncSetAttribute(attn_reg, cudaFuncAttributeMaxDynamicSharedMemorySize, ATTN3_SMEM);
    cudaFuncSetAttribute(gemm_fp16ca, cudaFuncAttributeMaxDynamicSharedMemorySize, GEMM_SMEM);

    // converts (bandwidth-bound)
    f2h_kernel<<<(S_LEN * HID) / (256 * 8), 256>>>(hidden, hid_h, S_LEN * HID);
    f2h_kernel<<<(P3 * HID) / (256 * 8), 256>>>(W_pack, wp_h, P3 * HID);
    f2h_kernel<<<(HID * HID) / (256 * 8), 256>>>(W_o, wo_h, HID * HID);

    // 1) QKV projection (fp16 cp.async + ldmatrix)
    gemm_fp16ca<<<dim3(P3 / 256, S_LEN / 128), 256, GEMM_SMEM>>>(hid_h, wp_h, proj,
                                                                 S_LEN, P3, HID);
    // 2) RoPE in-place on Q,K
    rope2_kernel<<<S_LEN, 256>>>(proj, pos_ids);
    // 3) causal flash attention (register-resident softmax, writes fp16)
    attn_reg<<<dim3(NH, S_LEN / 128), 256, ATTN3_SMEM>>>(proj, attn_h);
    // 4) output projection
    gemm_fp16ca<<<dim3(HID / 256, S_LEN / 128), 256, GEMM_SMEM>>>(attn_h, wo_h, out,
                                                                  S_LEN, HID, HID);
}